// round 7
// baseline (speedup 1.0000x reference)
#include <cuda_runtime.h>
#include <cuda_bf16.h>
#include <cuda_fp16.h>
#include <math.h>

#define MAXN 100000
#define MAXE 1600000

// ---------------- device scratch ----------------
__device__ uint2  g_h1h[MAXN * 32];   // layer1 features, fp16x4 per uint2 (128/node)
__device__ float4 g_x2v[MAXN * 32];   // layer1 output / layer2 input (fp32)
__device__ uint2  g_h2h[MAXN * 16];   // layer2 pre-agg features, fp16x4 (64/node)
__device__ float g_as1[MAXN * 4];
__device__ float g_ad1[MAXN * 4];
__device__ float g_as2[MAXN];
__device__ float g_ad2[MAXN];
__device__ int   g_xi[MAXN];
__device__ int   g_srcb[MAXE];
__device__ int   g_dstb[MAXE];
__device__ int   g_deg[MAXN];
__device__ int   g_off[MAXN + 1];
__device__ int   g_cur[MAXN];
__device__ int   g_csr[MAXE];
__device__ unsigned long long g_lb[512];   // decoupled-lookback state per scan block

// packed fp32x2 FMA (sm_10x; only reachable via PTX)
__device__ __forceinline__ void fma2(unsigned long long& acc,
                                     unsigned long long a,
                                     unsigned long long b) {
    asm("fma.rn.f32x2 %0, %1, %2, %0;" : "+l"(acc) : "l"(a), "l"(b));
}
__device__ __forceinline__ unsigned long long pk2(float lo, float hi) {
    unsigned long long r;
    asm("mov.b64 %0, {%1, %2};" : "=l"(r) : "f"(lo), "f"(hi));
    return r;
}
__device__ __forceinline__ float2 upk2(unsigned long long v) {
    float2 r;
    asm("mov.b64 {%0, %1}, %2;" : "=f"(r.x), "=f"(r.y) : "l"(v));
    return r;
}

// dtype sniff: x_indices = arange(N). int64 little-endian => word[1] (high half
// of element 0) == 0; int32 => word[1] == element 1 == 1.
__device__ __forceinline__ bool sniff64(const int* xw) { return xw[1] == 0; }

// ---------------- index normalization + scan-state reset ----------------
__global__ void k_conv_idx(const void* __restrict__ xidx, int n) {
    int i = blockIdx.x * blockDim.x + threadIdx.x;
    if (i < 512) g_lb[i] = 0ull;          // reset lookback state for this replay
    if (i >= n) return;
    bool is64 = sniff64((const int*)xidx);
    g_xi[i] = is64 ? (int)((const long long*)xidx)[i] : ((const int*)xidx)[i];
    g_deg[i] = 0;
}

__global__ void k_conv_ei(const void* __restrict__ ei,
                          const void* __restrict__ xidx, int e) {
    int i = blockIdx.x * blockDim.x + threadIdx.x;
    if (i >= e) return;
    bool is64 = sniff64((const int*)xidx);
    int s, d;
    if (is64) {
        s = (int)((const long long*)ei)[i];
        d = (int)((const long long*)ei)[(long long)e + i];
    } else {
        s = ((const int*)ei)[i];
        d = ((const int*)ei)[e + i];
    }
    g_srcb[i] = s;
    g_dstb[i] = d;
    atomicAdd(&g_deg[d], 1);
}

// ---------------- single-pass CSR-offset scan (decoupled lookback) ----------------
// All 391 blocks (100K threads) are co-resident on 148 SMs, so spinning on a
// predecessor's published state cannot deadlock.
__global__ void k_scan(int n, int etot) {
    __shared__ int s[256];
    __shared__ int s_prefix;
    int tid = threadIdx.x;
    int b = blockIdx.x;
    int i = b * 256 + tid;
    int v = (i < n) ? g_deg[i] : 0;
    s[tid] = v;
    __syncthreads();
    for (int o = 1; o < 256; o <<= 1) {
        int t = 0;
        if (tid >= o) t = s[tid - o];
        __syncthreads();
        s[tid] += t;
        __syncthreads();
    }
    int incl = s[tid];
    int agg = s[255];

    if (tid == 0) {
        // publish own aggregate (block 0 publishes final prefix directly)
        unsigned long long pub = (b == 0)
            ? ((2ull << 32) | (unsigned)agg)
            : ((1ull << 32) | (unsigned)agg);
        __threadfence();
        atomicExch(&g_lb[b], pub);

        int ex = 0;
        if (b > 0) {
            int p = b - 1;
            while (true) {
                unsigned long long st = atomicAdd(&g_lb[p], 0ull);
                unsigned flag = (unsigned)(st >> 32);
                if (flag == 2u) { ex += (int)(unsigned)st; break; }
                if (flag == 1u) { ex += (int)(unsigned)st; p--; }
            }
            __threadfence();
            atomicExch(&g_lb[b], (2ull << 32) | (unsigned)(ex + agg));
        }
        s_prefix = ex;
    }
    __syncthreads();
    int ex = s_prefix;
    if (i < n) {
        int o = ex + incl - v;
        g_off[i] = o;
        g_cur[i] = o;
        if (i == n - 1) g_off[n] = etot;
    }
}

// ---------------- GEMM + fused alpha epilogue (+ fused CSR scatter, layer 1) ----------------
// LAYER 1: X = emb[g_xi], W [128,128] -> fp16 g_h1h + as1/ad1 ; extra blocks do scatter
// LAYER 2: X = g_x2v,     W [128,64]  -> fp16 g_h2h + as2/ad2
template <int LAYER>
__global__ void __launch_bounds__(128) k_gemm(const float* __restrict__ Xin,
                                              const float* __restrict__ W,
                                              const float* __restrict__ asrc,
                                              const float* __restrict__ adst,
                                              int n, int gb, int e) {
    if (LAYER == 1 && (int)blockIdx.x >= gb) {
        int i = (blockIdx.x - gb) * 128 + threadIdx.x;
        if (i < e) {
            int pos = atomicAdd(&g_cur[g_dstb[i]], 1);
            g_csr[pos] = g_srcb[i];
        }
        return;
    }

    constexpr int COLS = (LAYER == 1) ? 128 : 64;
    constexpr int CT = COLS / 4;
    constexpr int NG = 128 / CT;
    constexpr int NPG = 64 / NG;

    __shared__ float4 Wsh[64 * CT];
    __shared__ float Xsh[64][64];

    const float* X = (LAYER == 1) ? Xin : (const float*)g_x2v;

    const int tid = threadIdx.x;
    const int tx = tid % CT;
    const int ty = tid / CT;
    const int base = blockIdx.x * 64;

    unsigned long long acc2[NPG][2];
#pragma unroll
    for (int i = 0; i < NPG; i++) { acc2[i][0] = 0ull; acc2[i][1] = 0ull; }

    const float4* W4 = (const float4*)W;

    for (int kb = 0; kb < 2; kb++) {
        __syncthreads();
#pragma unroll
        for (int idx = tid; idx < 64 * CT; idx += 128) {
            int row = idx / CT, col = idx % CT;
            Wsh[idx] = W4[(kb * 64 + row) * CT + col];
        }
#pragma unroll 8
        for (int idx = tid; idx < 64 * 64; idx += 128) {
            int r = idx >> 6, k = idx & 63;
            int node = base + r;
            float v = 0.f;
            if (node < n) {
                int g = (LAYER == 1) ? g_xi[node] : node;
                v = X[(long long)g * 128 + kb * 64 + k];
            }
            Xsh[r][k] = v;
        }
        __syncthreads();

#pragma unroll 2
        for (int k4 = 0; k4 < 16; k4++) {
            unsigned long long wlo[4], whi[4];
#pragma unroll
            for (int kk = 0; kk < 4; kk++) {
                float4 w = Wsh[(k4 * 4 + kk) * CT + tx];
                wlo[kk] = pk2(w.x, w.y);
                whi[kk] = pk2(w.z, w.w);
            }
#pragma unroll
            for (int i = 0; i < NPG; i++) {
                float4 xv = *(const float4*)&Xsh[ty * NPG + i][k4 * 4];
                unsigned long long xp;
                xp = pk2(xv.x, xv.x);
                fma2(acc2[i][0], wlo[0], xp);
                fma2(acc2[i][1], whi[0], xp);
                xp = pk2(xv.y, xv.y);
                fma2(acc2[i][0], wlo[1], xp);
                fma2(acc2[i][1], whi[1], xp);
                xp = pk2(xv.z, xv.z);
                fma2(acc2[i][0], wlo[2], xp);
                fma2(acc2[i][1], whi[2], xp);
                xp = pk2(xv.w, xv.w);
                fma2(acc2[i][0], wlo[3], xp);
                fma2(acc2[i][1], whi[3], xp);
            }
        }
    }

    const float4 as4 = ((const float4*)asrc)[tx];
    const float4 ad4 = ((const float4*)adst)[tx];
#pragma unroll
    for (int i = 0; i < NPG; i++) {
        int node = base + ty * NPG + i;
        if (node >= n) continue;
        float2 lo = upk2(acc2[i][0]);
        float2 hi = upk2(acc2[i][1]);

        float s = lo.x * as4.x + lo.y * as4.y + hi.x * as4.z + hi.y * as4.w;
        float d = lo.x * ad4.x + lo.y * ad4.y + hi.x * ad4.z + hi.y * ad4.w;

        uint2 p;
        __half2 h0 = __float22half2_rn(make_float2(lo.x, lo.y));
        __half2 h1 = __float22half2_rn(make_float2(hi.x, hi.y));
        p.x = *(unsigned int*)&h0;
        p.y = *(unsigned int*)&h1;

        if (LAYER == 1) {
            g_h1h[node * 32 + tx] = p;
#pragma unroll
            for (int o = 1; o < 8; o <<= 1) {
                s += __shfl_xor_sync(0xffffffffu, s, o);
                d += __shfl_xor_sync(0xffffffffu, d, o);
            }
            if ((tx & 7) == 0) {
                g_as1[node * 4 + (tx >> 3)] = s;
                g_ad1[node * 4 + (tx >> 3)] = d;
            }
        } else {
            g_h2h[node * 16 + tx] = p;
#pragma unroll
            for (int o = 1; o < 16; o <<= 1) {
                s += __shfl_xor_sync(0xffffffffu, s, o);
                d += __shfl_xor_sync(0xffffffffu, d, o);
            }
            if (tx == 0) {
                g_as2[node] = s;
                g_ad2[node] = d;
            }
        }
    }
}

__device__ __forceinline__ float att_w(float e) {
    float lr = (e > 0.f) ? e : 0.2f * e;
    return __expf(lr);
}

// ---------------- fused gather layer 1 (fp16): softmax-agg + bias + ELU ----------------
__global__ void k_gather1(const float* __restrict__ b1, int n) {
    int node = (blockIdx.x * blockDim.x + threadIdx.x) >> 5;
    int lane = threadIdx.x & 31;
    if (node >= n) return;
    int head = lane >> 3;

    float ad = g_ad1[node * 4 + head];

    float w = att_w(g_as1[node * 4 + head] + ad);
    uint2 p = g_h1h[node * 32 + lane];
    float2 f0 = __half22float2(*(const __half2*)&p.x);
    float2 f1 = __half22float2(*(const __half2*)&p.y);
    float4 acc = make_float4(w * f0.x, w * f0.y, w * f1.x, w * f1.y);
    float wsum = w;

    int i = g_off[node];
    int iend = g_off[node + 1];
    for (; i < iend; i++) {
        int src = g_csr[i];
        float ww = att_w(g_as1[src * 4 + head] + ad);
        uint2 q = g_h1h[src * 32 + lane];
        float2 v0 = __half22float2(*(const __half2*)&q.x);
        float2 v1 = __half22float2(*(const __half2*)&q.y);
        acc.x += ww * v0.x;
        acc.y += ww * v0.y;
        acc.z += ww * v1.x;
        acc.w += ww * v1.y;
        wsum += ww;
    }
    float inv = 1.f / wsum;
    float4 bb = ((const float4*)b1)[lane];
    float ox = acc.x * inv + bb.x;
    float oy = acc.y * inv + bb.y;
    float oz = acc.z * inv + bb.z;
    float ow = acc.w * inv + bb.w;
    ox = (ox > 0.f) ? ox : expm1f(ox);
    oy = (oy > 0.f) ? oy : expm1f(oy);
    oz = (oz > 0.f) ? oz : expm1f(oz);
    ow = (ow > 0.f) ? ow : expm1f(ow);
    g_x2v[node * 32 + lane] = make_float4(ox, oy, oz, ow);
}

// ---------------- fused gather layer 2 (fp16): softmax-agg + bias ----------------
__global__ void k_gather2(const float* __restrict__ b2, float* __restrict__ out, int n) {
    int node = (blockIdx.x * blockDim.x + threadIdx.x) >> 5;
    int lane = threadIdx.x & 31;
    if (node >= n) return;

    const __half2* H2 = (const __half2*)g_h2h;
    float ad = g_ad2[node];

    float w = att_w(g_as2[node] + ad);
    float2 hv = __half22float2(H2[node * 32 + lane]);
    float2 acc = make_float2(w * hv.x, w * hv.y);
    float wsum = w;

    int i = g_off[node];
    int iend = g_off[node + 1];
    for (; i < iend; i++) {
        int src = g_csr[i];
        float ww = att_w(g_as2[src] + ad);
        float2 v = __half22float2(H2[src * 32 + lane]);
        acc.x += ww * v.x;
        acc.y += ww * v.y;
        wsum += ww;
    }
    float inv = 1.f / wsum;
    float2 bb = ((const float2*)b2)[lane];
    ((float2*)out)[node * 32 + lane] =
        make_float2(acc.x * inv + bb.x, acc.y * inv + bb.y);
}

// ---------------- launch ----------------
extern "C" void kernel_launch(void* const* d_in, const int* in_sizes, int n_in,
                              void* d_out, int out_size) {
    const void* xidx = d_in[0];
    const void* ei = d_in[1];
    const float* emb = (const float*)d_in[2];
    const float* W1 = (const float*)d_in[3];
    const float* a_src1 = (const float*)d_in[4];
    const float* a_dst1 = (const float*)d_in[5];
    const float* b1 = (const float*)d_in[6];
    const float* W2 = (const float*)d_in[7];
    const float* a_src2 = (const float*)d_in[8];
    const float* a_dst2 = (const float*)d_in[9];
    const float* b2 = (const float*)d_in[10];
    float* out = (float*)d_out;

    int n = in_sizes[0];
    int e = in_sizes[1] / 2;

    int nb256 = (n + 255) / 256;
    int eb256 = (e + 255) / 256;
    int nwarp = (n + 7) / 8;
    int gb = (n + 63) / 64;
    int eb128 = (e + 127) / 128;

    k_conv_idx<<<nb256, 256>>>(xidx, n);
    k_conv_ei<<<eb256, 256>>>(ei, xidx, e);
    k_scan<<<nb256, 256>>>(n, e);          // single-pass decoupled-lookback scan

    k_gemm<1><<<gb + eb128, 128>>>(emb, W1, a_src1, a_dst1, n, gb, e);
    k_gather1<<<nwarp, 256>>>(b1, n);

    k_gemm<2><<<gb, 128>>>(nullptr, W2, a_src2, a_dst2, n, gb, 0);
    k_gather2<<<nwarp, 256>>>(b2, out, n);
}

// round 8
// speedup vs baseline: 1.0288x; 1.0288x over previous
#include <cuda_runtime.h>
#include <cuda_bf16.h>
#include <cuda_fp16.h>
#include <math.h>

#define MAXN 100000
#define MAXE 1600000

// ---------------- device scratch ----------------
__device__ uint2  g_h1h[MAXN * 32];   // layer1 features, fp16x4 per uint2 (128/node)
__device__ float4 g_x2v[MAXN * 32];   // layer1 output / layer2 input (fp32)
__device__ uint2  g_h2h[MAXN * 16];   // layer2 pre-agg features, fp16x4 (64/node)
__device__ float g_as1[MAXN * 4];
__device__ float g_ad1[MAXN * 4];
__device__ float g_as2[MAXN];
__device__ float g_ad2[MAXN];
__device__ int   g_xi[MAXN];
__device__ int   g_srcb[MAXE];
__device__ int   g_dstb[MAXE];
__device__ int   g_deg[MAXN];
__device__ int   g_off[MAXN + 1];
__device__ int   g_cur[MAXN];
__device__ int   g_csr[MAXE];
__device__ unsigned long long g_lb[512];   // decoupled-lookback state

// packed fp32x2 FMA (sm_10x; only reachable via PTX)
__device__ __forceinline__ void fma2(unsigned long long& acc,
                                     unsigned long long a,
                                     unsigned long long b) {
    asm("fma.rn.f32x2 %0, %1, %2, %0;" : "+l"(acc) : "l"(a), "l"(b));
}
__device__ __forceinline__ unsigned long long pk2(float lo, float hi) {
    unsigned long long r;
    asm("mov.b64 %0, {%1, %2};" : "=l"(r) : "f"(lo), "f"(hi));
    return r;
}
__device__ __forceinline__ float2 upk2(unsigned long long v) {
    float2 r;
    asm("mov.b64 {%0, %1}, %2;" : "=f"(r.x), "=f"(r.y) : "l"(v));
    return r;
}

// dtype sniff: x_indices = arange(N). int64 little-endian => word[1] == 0.
__device__ __forceinline__ bool sniff64(const int* xw) { return xw[1] == 0; }

// ---------------- index normalization + lookback-state reset ----------------
__global__ void k_conv_idx(const void* __restrict__ xidx, int n) {
    int i = blockIdx.x * blockDim.x + threadIdx.x;
    if (i < 512) g_lb[i] = 0ull;
    if (i >= n) return;
    bool is64 = sniff64((const int*)xidx);
    g_xi[i] = is64 ? (int)((const long long*)xidx)[i] : ((const int*)xidx)[i];
    g_deg[i] = 0;
}

__global__ void k_conv_ei(const void* __restrict__ ei,
                          const void* __restrict__ xidx, int e) {
    int i = blockIdx.x * blockDim.x + threadIdx.x;
    if (i >= e) return;
    bool is64 = sniff64((const int*)xidx);
    int s, d;
    if (is64) {
        s = (int)((const long long*)ei)[i];
        d = (int)((const long long*)ei)[(long long)e + i];
    } else {
        s = ((const int*)ei)[i];
        d = ((const int*)ei)[e + i];
    }
    g_srcb[i] = s;
    g_dstb[i] = d;
    atomicAdd(&g_deg[d], 1);
}

// ---------------- single-pass scan, warp-parallel decoupled lookback ----------------
__global__ void k_scan(int n, int etot) {
    __shared__ int s[256];
    __shared__ int s_prefix;
    int tid = threadIdx.x;
    int b = blockIdx.x;
    int i = b * 256 + tid;
    int v = (i < n) ? g_deg[i] : 0;
    s[tid] = v;
    __syncthreads();
    for (int o = 1; o < 256; o <<= 1) {
        int t = 0;
        if (tid >= o) t = s[tid - o];
        __syncthreads();
        s[tid] += t;
        __syncthreads();
    }
    int incl = s[tid];
    int agg = s[255];

    if (tid < 32) {
        if (tid == 0) {
            unsigned long long pub = (b == 0)
                ? ((2ull << 32) | (unsigned)agg)
                : ((1ull << 32) | (unsigned)agg);
            __threadfence();
            atomicExch(&g_lb[b], pub);
        }
        int ex = 0;
        if (b > 0) {
            int p = b - 1;
            while (true) {
                int idx = p - (int)tid;
                unsigned long long st = (idx >= 0) ? atomicAdd(&g_lb[idx], 0ull)
                                                   : (2ull << 32);  // prefix 0
                unsigned flag = (unsigned)(st >> 32);
                if (__any_sync(0xffffffffu, flag == 0u)) continue;   // not yet published
                unsigned m2 = __ballot_sync(0xffffffffu, flag == 2u);
                int contrib;
                if (m2) {
                    int L = __ffs(m2) - 1;          // nearest finished prefix
                    contrib = ((int)tid <= L) ? (int)(unsigned)st : 0;
                } else {
                    contrib = (int)(unsigned)st;     // all partial: take whole window
                }
#pragma unroll
                for (int o = 16; o > 0; o >>= 1)
                    contrib += __shfl_xor_sync(0xffffffffu, contrib, o);
                ex += contrib;
                if (m2) break;
                p -= 32;
            }
            if (tid == 0) {
                __threadfence();
                atomicExch(&g_lb[b], (2ull << 32) | (unsigned)(ex + agg));
            }
        }
        if (tid == 0) s_prefix = ex;
    }
    __syncthreads();
    int ex = s_prefix;
    if (i < n) {
        int o = ex + incl - v;
        g_off[i] = o;
        g_cur[i] = o;
        if (i == n - 1) g_off[n] = etot;
    }
}

// ---------------- GEMM + fused alpha epilogue (+ fused CSR scatter, layer 1) ----------------
// Thread tile 8 nodes x 8 cols: per-k4 LDS = 8 X + 8 W float4 -> balanced vs FMA.
// LAYER 1: block 64 nodes x 128 cols ; LAYER 2: block 128 nodes x 64 cols.
template <int LAYER>
__global__ void __launch_bounds__(128) k_gemm(const float* __restrict__ Xin,
                                              const float* __restrict__ W,
                                              const float* __restrict__ asrc,
                                              const float* __restrict__ adst,
                                              int n, int gb, int e) {
    if (LAYER == 1 && (int)blockIdx.x >= gb) {
        int i = (blockIdx.x - gb) * 128 + threadIdx.x;
        if (i < e) {
            int pos = atomicAdd(&g_cur[g_dstb[i]], 1);
            g_csr[pos] = g_srcb[i];
        }
        return;
    }

    constexpr int COLS = (LAYER == 1) ? 128 : 64;
    constexpr int CT = COLS / 8;      // threads across cols (8 cols each): 16 / 8
    constexpr int NG = 128 / CT;      // node groups: 8 / 16
    constexpr int NPB = NG * 8;       // nodes per block: 64 / 128
    constexpr int WROW = COLS / 4;    // float4 per W row: 32 / 16

    __shared__ float4 Wsh[64 * WROW]; // one K-chunk of W
    __shared__ float Xsh[NPB][64];    // one K-chunk of X

    const float* X = (LAYER == 1) ? Xin : (const float*)g_x2v;

    const int tid = threadIdx.x;
    const int tx = tid % CT;
    const int ty = tid / CT;
    const int base = blockIdx.x * NPB;

    unsigned long long acc[8][4];
#pragma unroll
    for (int i = 0; i < 8; i++)
#pragma unroll
        for (int c = 0; c < 4; c++) acc[i][c] = 0ull;

    const float4* W4 = (const float4*)W;
    const float4* X4 = (const float4*)X;

    for (int kb = 0; kb < 2; kb++) {
        __syncthreads();
#pragma unroll 4
        for (int idx = tid; idx < 64 * WROW; idx += 128)
            Wsh[idx] = W4[(kb * 64 + idx / WROW) * WROW + idx % WROW];
#pragma unroll 4
        for (int idx = tid; idx < NPB * 16; idx += 128) {
            int r = idx >> 4, f4 = idx & 15;
            int node = base + r;
            float4 v = make_float4(0.f, 0.f, 0.f, 0.f);
            if (node < n) {
                int g = (LAYER == 1) ? g_xi[node] : node;
                v = X4[(long long)g * 32 + kb * 16 + f4];
            }
            *(float4*)&Xsh[r][f4 * 4] = v;
        }
        __syncthreads();

        for (int k4 = 0; k4 < 16; k4++) {
            unsigned long long wv[4][4];
#pragma unroll
            for (int kk = 0; kk < 4; kk++) {
                float4 a = Wsh[(k4 * 4 + kk) * WROW + tx * 2];
                float4 bq = Wsh[(k4 * 4 + kk) * WROW + tx * 2 + 1];
                wv[kk][0] = pk2(a.x, a.y);
                wv[kk][1] = pk2(a.z, a.w);
                wv[kk][2] = pk2(bq.x, bq.y);
                wv[kk][3] = pk2(bq.z, bq.w);
            }
#pragma unroll
            for (int i = 0; i < 8; i++) {
                float4 xv = *(const float4*)&Xsh[ty * 8 + i][k4 * 4];
                unsigned long long xp;
                xp = pk2(xv.x, xv.x);
                fma2(acc[i][0], wv[0][0], xp);
                fma2(acc[i][1], wv[0][1], xp);
                fma2(acc[i][2], wv[0][2], xp);
                fma2(acc[i][3], wv[0][3], xp);
                xp = pk2(xv.y, xv.y);
                fma2(acc[i][0], wv[1][0], xp);
                fma2(acc[i][1], wv[1][1], xp);
                fma2(acc[i][2], wv[1][2], xp);
                fma2(acc[i][3], wv[1][3], xp);
                xp = pk2(xv.z, xv.z);
                fma2(acc[i][0], wv[2][0], xp);
                fma2(acc[i][1], wv[2][1], xp);
                fma2(acc[i][2], wv[2][2], xp);
                fma2(acc[i][3], wv[2][3], xp);
                xp = pk2(xv.w, xv.w);
                fma2(acc[i][0], wv[3][0], xp);
                fma2(acc[i][1], wv[3][1], xp);
                fma2(acc[i][2], wv[3][2], xp);
                fma2(acc[i][3], wv[3][3], xp);
            }
        }
    }

    // epilogue: fp16 store + fused attention-logit reduction
    const float4 asa = ((const float4*)asrc)[tx * 2];
    const float4 asb = ((const float4*)asrc)[tx * 2 + 1];
    const float4 ada = ((const float4*)adst)[tx * 2];
    const float4 adb = ((const float4*)adst)[tx * 2 + 1];
#pragma unroll
    for (int i = 0; i < 8; i++) {
        int node = base + ty * 8 + i;
        if (node >= n) continue;
        float2 c0 = upk2(acc[i][0]);
        float2 c1 = upk2(acc[i][1]);
        float2 c2 = upk2(acc[i][2]);
        float2 c3 = upk2(acc[i][3]);

        float s = c0.x * asa.x + c0.y * asa.y + c1.x * asa.z + c1.y * asa.w
                + c2.x * asb.x + c2.y * asb.y + c3.x * asb.z + c3.y * asb.w;
        float d = c0.x * ada.x + c0.y * ada.y + c1.x * ada.z + c1.y * ada.w
                + c2.x * adb.x + c2.y * adb.y + c3.x * adb.z + c3.y * adb.w;

        uint2 p0, p1;
        __half2 h0 = __float22half2_rn(c0);
        __half2 h1 = __float22half2_rn(c1);
        __half2 h2 = __float22half2_rn(c2);
        __half2 h3 = __float22half2_rn(c3);
        p0.x = *(unsigned int*)&h0;
        p0.y = *(unsigned int*)&h1;
        p1.x = *(unsigned int*)&h2;
        p1.y = *(unsigned int*)&h3;

        if (LAYER == 1) {
            g_h1h[node * 32 + tx * 2] = p0;
            g_h1h[node * 32 + tx * 2 + 1] = p1;
            // head = tx/4 (8 cols per thread, 32 per head); reduce over 4 col-threads
#pragma unroll
            for (int o = 1; o < 4; o <<= 1) {
                s += __shfl_xor_sync(0xffffffffu, s, o);
                d += __shfl_xor_sync(0xffffffffu, d, o);
            }
            if ((tx & 3) == 0) {
                g_as1[node * 4 + (tx >> 2)] = s;
                g_ad1[node * 4 + (tx >> 2)] = d;
            }
        } else {
            g_h2h[node * 16 + tx * 2] = p0;
            g_h2h[node * 16 + tx * 2 + 1] = p1;
            // single head: reduce over all 8 col-threads
#pragma unroll
            for (int o = 1; o < 8; o <<= 1) {
                s += __shfl_xor_sync(0xffffffffu, s, o);
                d += __shfl_xor_sync(0xffffffffu, d, o);
            }
            if (tx == 0) {
                g_as2[node] = s;
                g_ad2[node] = d;
            }
        }
    }
}

__device__ __forceinline__ float att_w(float e) {
    float lr = (e > 0.f) ? e : 0.2f * e;
    return __expf(lr);
}

// ---------------- fused gather layer 1 (fp16): softmax-agg + bias + ELU ----------------
__global__ void k_gather1(const float* __restrict__ b1, int n) {
    int node = (blockIdx.x * blockDim.x + threadIdx.x) >> 5;
    int lane = threadIdx.x & 31;
    if (node >= n) return;
    int head = lane >> 3;

    float ad = g_ad1[node * 4 + head];

    float w = att_w(g_as1[node * 4 + head] + ad);
    uint2 p = g_h1h[node * 32 + lane];
    float2 f0 = __half22float2(*(const __half2*)&p.x);
    float2 f1 = __half22float2(*(const __half2*)&p.y);
    float4 acc = make_float4(w * f0.x, w * f0.y, w * f1.x, w * f1.y);
    float wsum = w;

    int i = g_off[node];
    int iend = g_off[node + 1];
    for (; i < iend; i++) {
        int src = g_csr[i];
        float ww = att_w(g_as1[src * 4 + head] + ad);
        uint2 q = g_h1h[src * 32 + lane];
        float2 v0 = __half22float2(*(const __half2*)&q.x);
        float2 v1 = __half22float2(*(const __half2*)&q.y);
        acc.x += ww * v0.x;
        acc.y += ww * v0.y;
        acc.z += ww * v1.x;
        acc.w += ww * v1.y;
        wsum += ww;
    }
    float inv = 1.f / wsum;
    float4 bb = ((const float4*)b1)[lane];
    float ox = acc.x * inv + bb.x;
    float oy = acc.y * inv + bb.y;
    float oz = acc.z * inv + bb.z;
    float ow = acc.w * inv + bb.w;
    ox = (ox > 0.f) ? ox : expm1f(ox);
    oy = (oy > 0.f) ? oy : expm1f(oy);
    oz = (oz > 0.f) ? oz : expm1f(oz);
    ow = (ow > 0.f) ? ow : expm1f(ow);
    g_x2v[node * 32 + lane] = make_float4(ox, oy, oz, ow);
}

// ---------------- fused gather layer 2 (fp16): softmax-agg + bias ----------------
__global__ void k_gather2(const float* __restrict__ b2, float* __restrict__ out, int n) {
    int node = (blockIdx.x * blockDim.x + threadIdx.x) >> 5;
    int lane = threadIdx.x & 31;
    if (node >= n) return;

    const __half2* H2 = (const __half2*)g_h2h;
    float ad = g_ad2[node];

    float w = att_w(g_as2[node] + ad);
    float2 hv = __half22float2(H2[node * 32 + lane]);
    float2 acc = make_float2(w * hv.x, w * hv.y);
    float wsum = w;

    int i = g_off[node];
    int iend = g_off[node + 1];
    for (; i < iend; i++) {
        int src = g_csr[i];
        float ww = att_w(g_as2[src] + ad);
        float2 v = __half22float2(H2[src * 32 + lane]);
        acc.x += ww * v.x;
        acc.y += ww * v.y;
        wsum += ww;
    }
    float inv = 1.f / wsum;
    float2 bb = ((const float2*)b2)[lane];
    ((float2*)out)[node * 32 + lane] =
        make_float2(acc.x * inv + bb.x, acc.y * inv + bb.y);
}

// ---------------- launch ----------------
extern "C" void kernel_launch(void* const* d_in, const int* in_sizes, int n_in,
                              void* d_out, int out_size) {
    const void* xidx = d_in[0];
    const void* ei = d_in[1];
    const float* emb = (const float*)d_in[2];
    const float* W1 = (const float*)d_in[3];
    const float* a_src1 = (const float*)d_in[4];
    const float* a_dst1 = (const float*)d_in[5];
    const float* b1 = (const float*)d_in[6];
    const float* W2 = (const float*)d_in[7];
    const float* a_src2 = (const float*)d_in[8];
    const float* a_dst2 = (const float*)d_in[9];
    const float* b2 = (const float*)d_in[10];
    float* out = (float*)d_out;

    int n = in_sizes[0];
    int e = in_sizes[1] / 2;

    int nb256 = (n + 255) / 256;
    int eb256 = (e + 255) / 256;
    int nwarp = (n + 7) / 8;
    int gb1 = (n + 63) / 64;      // layer-1 GEMM blocks (64 nodes each)
    int gb2 = (n + 127) / 128;    // layer-2 GEMM blocks (128 nodes each)
    int eb128 = (e + 127) / 128;

    k_conv_idx<<<nb256, 256>>>(xidx, n);
    k_conv_ei<<<eb256, 256>>>(ei, xidx, e);
    k_scan<<<nb256, 256>>>(n, e);

    k_gemm<1><<<gb1 + eb128, 128>>>(emb, W1, a_src1, a_dst1, n, gb1, e);
    k_gather1<<<nwarp, 256>>>(b1, n);

    k_gemm<2><<<gb2, 128>>>(nullptr, W2, a_src2, a_dst2, n, gb2, 0);
    k_gather2<<<nwarp, 256>>>(b2, out, n);
}

// round 9
// speedup vs baseline: 1.3076x; 1.2710x over previous
#include <cuda_runtime.h>
#include <cuda_bf16.h>
#include <cuda_fp16.h>
#include <math.h>

#define MAXN 100000
#define MAXE 1600000

// ---------------- device scratch ----------------
__device__ uint2  g_h1h[MAXN * 32];   // layer1 features, fp16x4 per uint2 (128/node)
__device__ uint2  g_x2h[MAXN * 32];   // layer1 output (fp16), layer2 GEMM input
__device__ uint2  g_h2h[MAXN * 16];   // layer2 pre-agg features, fp16x4 (64/node)
__device__ __align__(16) __half g_w1t[128 * 128];  // W1^T fp16 (n-major)
__device__ __align__(16) __half g_w2t[64 * 128];   // W2^T fp16 (n-major)
__device__ float g_as1[MAXN * 4];
__device__ float g_ad1[MAXN * 4];
__device__ float g_as2[MAXN];
__device__ float g_ad2[MAXN];
__device__ int   g_xi[MAXN];
__device__ int   g_srcb[MAXE];
__device__ int   g_dstb[MAXE];
__device__ int   g_deg[MAXN];
__device__ int   g_off[MAXN + 1];
__device__ int   g_cur[MAXN];
__device__ int   g_csr[MAXE];
__device__ unsigned long long g_lb[512];

// dtype sniff: x_indices = arange(N). int64 little-endian => word[1] == 0.
__device__ __forceinline__ bool sniff64(const int* xw) { return xw[1] == 0; }

// 16B-chunk swizzle: row-local XOR keeps ldmatrix column reads conflict-free.
__device__ __forceinline__ int swz(int row, int ch) {
    return (row * 16 + (ch ^ (row & 15))) << 4;   // byte offset
}

__device__ __forceinline__ void ldsm4(unsigned& r0, unsigned& r1,
                                      unsigned& r2, unsigned& r3, unsigned addr) {
    asm volatile("ldmatrix.sync.aligned.m8n8.x4.shared.b16 {%0,%1,%2,%3}, [%4];"
                 : "=r"(r0), "=r"(r1), "=r"(r2), "=r"(r3) : "r"(addr));
}
__device__ __forceinline__ void mma16816(float* c, unsigned a0, unsigned a1,
                                         unsigned a2, unsigned a3,
                                         unsigned b0, unsigned b1) {
    asm volatile(
        "mma.sync.aligned.m16n8k16.row.col.f32.f16.f16.f32 "
        "{%0,%1,%2,%3}, {%4,%5,%6,%7}, {%8,%9}, {%0,%1,%2,%3};"
        : "+f"(c[0]), "+f"(c[1]), "+f"(c[2]), "+f"(c[3])
        : "r"(a0), "r"(a1), "r"(a2), "r"(a3), "r"(b0), "r"(b1));
}

// ---------------- index normalization + W transpose/convert + lb reset ----------------
__global__ void k_conv_idx(const void* __restrict__ xidx,
                           const float* __restrict__ W1,
                           const float* __restrict__ W2, int n) {
    int i = blockIdx.x * blockDim.x + threadIdx.x;
    if (i < 512) g_lb[i] = 0ull;
    if (i < 128 * 128) {
        int nn = i >> 7, k = i & 127;
        g_w1t[i] = __float2half(W1[k * 128 + nn]);
    }
    if (i < 64 * 128) {
        int nn = i >> 7, k = i & 127;
        g_w2t[i] = __float2half(W2[k * 64 + nn]);
    }
    if (i >= n) return;
    bool is64 = sniff64((const int*)xidx);
    g_xi[i] = is64 ? (int)((const long long*)xidx)[i] : ((const int*)xidx)[i];
    g_deg[i] = 0;
}

__global__ void k_conv_ei(const void* __restrict__ ei,
                          const void* __restrict__ xidx, int e) {
    int i = blockIdx.x * blockDim.x + threadIdx.x;
    if (i >= e) return;
    bool is64 = sniff64((const int*)xidx);
    int s, d;
    if (is64) {
        s = (int)((const long long*)ei)[i];
        d = (int)((const long long*)ei)[(long long)e + i];
    } else {
        s = ((const int*)ei)[i];
        d = ((const int*)ei)[e + i];
    }
    g_srcb[i] = s;
    g_dstb[i] = d;
    atomicAdd(&g_deg[d], 1);
}

// ---------------- single-pass scan, warp-parallel decoupled lookback ----------------
__global__ void k_scan(int n, int etot) {
    __shared__ int s[256];
    __shared__ int s_prefix;
    int tid = threadIdx.x;
    int b = blockIdx.x;
    int i = b * 256 + tid;
    int v = (i < n) ? g_deg[i] : 0;
    s[tid] = v;
    __syncthreads();
    for (int o = 1; o < 256; o <<= 1) {
        int t = 0;
        if (tid >= o) t = s[tid - o];
        __syncthreads();
        s[tid] += t;
        __syncthreads();
    }
    int incl = s[tid];
    int agg = s[255];

    if (tid < 32) {
        if (tid == 0) {
            unsigned long long pub = (b == 0)
                ? ((2ull << 32) | (unsigned)agg)
                : ((1ull << 32) | (unsigned)agg);
            __threadfence();
            atomicExch(&g_lb[b], pub);
        }
        int ex = 0;
        if (b > 0) {
            int p = b - 1;
            while (true) {
                int idx = p - (int)tid;
                unsigned long long st = (idx >= 0) ? atomicAdd(&g_lb[idx], 0ull)
                                                   : (2ull << 32);
                unsigned flag = (unsigned)(st >> 32);
                if (__any_sync(0xffffffffu, flag == 0u)) continue;
                unsigned m2 = __ballot_sync(0xffffffffu, flag == 2u);
                int contrib;
                if (m2) {
                    int L = __ffs(m2) - 1;
                    contrib = ((int)tid <= L) ? (int)(unsigned)st : 0;
                } else {
                    contrib = (int)(unsigned)st;
                }
#pragma unroll
                for (int o = 16; o > 0; o >>= 1)
                    contrib += __shfl_xor_sync(0xffffffffu, contrib, o);
                ex += contrib;
                if (m2) break;
                p -= 32;
            }
            if (tid == 0) {
                __threadfence();
                atomicExch(&g_lb[b], (2ull << 32) | (unsigned)(ex + agg));
            }
        }
        if (tid == 0) s_prefix = ex;
    }
    __syncthreads();
    int ex = s_prefix;
    if (i < n) {
        int o = ex + incl - v;
        g_off[i] = o;
        g_cur[i] = o;
        if (i == n - 1) g_off[n] = etot;
    }
}

// ---------------- tensor-core GEMM + fused alpha epilogue (+ scatter, layer 1) -------
// Block = 64 nodes (4 warps x 16). LAYER 1: 128 cols; LAYER 2: 64 cols. K = 128.
template <int LAYER>
__global__ void __launch_bounds__(128) k_gemm(const float* __restrict__ Xin,
                                              const float* __restrict__ asrc,
                                              const float* __restrict__ adst,
                                              int n, int gb, int e) {
    if (LAYER == 1 && (int)blockIdx.x >= gb) {
        int i = (blockIdx.x - gb) * 128 + threadIdx.x;
        if (i < e) {
            int pos = atomicAdd(&g_cur[g_dstb[i]], 1);
            g_csr[pos] = g_srcb[i];
        }
        return;
    }

    constexpr int COLS = (LAYER == 1) ? 128 : 64;
    constexpr int NT = COLS / 8;            // n-tiles per warp: 16 / 8
    constexpr int CPAD = COLS + 4;
    constexpr int BROWS = COLS;             // B rows (n) = COLS
    constexpr int SBYTES = 16384 + BROWS * 256;  // A(16K) + B

    __shared__ __align__(16) char sbuf[SBYTES];
    char* Ab = sbuf;
    char* Bb = sbuf + 16384;

    const int tid = threadIdx.x;
    const int lane = tid & 31;
    const int wid = tid >> 5;
    const int base = blockIdx.x * 64;

    // ---- stage A (64 nodes x 128 k, fp16, swizzled) ----
    if (LAYER == 1) {
        const float4* E4 = (const float4*)Xin;
        for (int idx = tid; idx < 64 * 16; idx += 128) {
            int r = idx >> 4, ch = idx & 15;
            int node = base + r;
            uint4 val = make_uint4(0, 0, 0, 0);
            if (node < n) {
                long long g = g_xi[node];
                float4 x0 = E4[g * 32 + ch * 2];
                float4 x1 = E4[g * 32 + ch * 2 + 1];
                __half2 h0 = __float22half2_rn(make_float2(x0.x, x0.y));
                __half2 h1 = __float22half2_rn(make_float2(x0.z, x0.w));
                __half2 h2 = __float22half2_rn(make_float2(x1.x, x1.y));
                __half2 h3 = __float22half2_rn(make_float2(x1.z, x1.w));
                val.x = *(unsigned*)&h0;
                val.y = *(unsigned*)&h1;
                val.z = *(unsigned*)&h2;
                val.w = *(unsigned*)&h3;
            }
            *(uint4*)(Ab + swz(r, ch)) = val;
        }
    } else {
        for (int idx = tid; idx < 64 * 16; idx += 128) {
            int r = idx >> 4, ch = idx & 15;
            int node = base + r;
            uint4 val = make_uint4(0, 0, 0, 0);
            if (node < n) {
                uint2 v0 = g_x2h[node * 32 + ch * 2];
                uint2 v1 = g_x2h[node * 32 + ch * 2 + 1];
                val = make_uint4(v0.x, v0.y, v1.x, v1.y);
            }
            *(uint4*)(Ab + swz(r, ch)) = val;
        }
    }
    // ---- stage B = W^T (COLS n-rows x 128 k, fp16, swizzled) ----
    {
        const uint4* Wt = (const uint4*)((LAYER == 1) ? g_w1t : g_w2t);
        for (int idx = tid; idx < BROWS * 16; idx += 128) {
            int r = idx >> 4, ch = idx & 15;
            *(uint4*)(Bb + swz(r, ch)) = Wt[r * 16 + ch];
        }
    }
    __syncthreads();

    // ---- mma mainloop ----
    float c[NT][4];
#pragma unroll
    for (int j = 0; j < NT; j++)
#pragma unroll
        for (int q = 0; q < 4; q++) c[j][q] = 0.f;

    const int m0 = wid * 16;
    const int tl = lane >> 3;      // ldmatrix tile id
    const int rr = lane & 7;
    unsigned a_u = (unsigned)__cvta_generic_to_shared(Ab);
    unsigned b_u = (unsigned)__cvta_generic_to_shared(Bb);

#pragma unroll
    for (int s = 0; s < 8; s++) {
        int chunk = 2 * s + (tl >> 1);
        unsigned a0, a1, a2, a3;
        ldsm4(a0, a1, a2, a3, a_u + swz(m0 + (tl & 1) * 8 + rr, chunk));
#pragma unroll
        for (int t = 0; t < NT / 2; t++) {
            unsigned r0, r1, r2, r3;
            ldsm4(r0, r1, r2, r3, b_u + swz(t * 16 + (tl & 1) * 8 + rr, chunk));
            mma16816(c[2 * t], a0, a1, a2, a3, r0, r2);
            mma16816(c[2 * t + 1], a0, a1, a2, a3, r1, r3);
        }
    }

    // ---- epilogue: frags -> smem, then per-node logit reduce + fp16 store ----
    __syncthreads();                       // done reading A/B; overlay C
    float* Cw = (float*)sbuf + wid * 16 * CPAD;
    {
        int g = lane >> 2, tg = lane & 3;
#pragma unroll
        for (int j = 0; j < NT; j++) {
            *(float2*)&Cw[g * CPAD + j * 8 + 2 * tg] = make_float2(c[j][0], c[j][1]);
            *(float2*)&Cw[(g + 8) * CPAD + j * 8 + 2 * tg] = make_float2(c[j][2], c[j][3]);
        }
    }
    __syncwarp();

    if (LAYER == 1) {
        const float4 as4 = ((const float4*)asrc)[lane];   // cols lane*4..+3
        const float4 ad4 = ((const float4*)adst)[lane];
        for (int r2 = 0; r2 < 16; r2++) {
            int node = base + m0 + r2;
            if (node >= n) break;
            float4 cv = *(float4*)&Cw[r2 * CPAD + lane * 4];
            float s = cv.x * as4.x + cv.y * as4.y + cv.z * as4.z + cv.w * as4.w;
            float d = cv.x * ad4.x + cv.y * ad4.y + cv.z * ad4.z + cv.w * ad4.w;
#pragma unroll
            for (int o = 1; o < 8; o <<= 1) {
                s += __shfl_xor_sync(0xffffffffu, s, o);
                d += __shfl_xor_sync(0xffffffffu, d, o);
            }
            if ((lane & 7) == 0) {
                g_as1[node * 4 + (lane >> 3)] = s;
                g_ad1[node * 4 + (lane >> 3)] = d;
            }
            __half2 h0 = __float22half2_rn(make_float2(cv.x, cv.y));
            __half2 h1 = __float22half2_rn(make_float2(cv.z, cv.w));
            g_h1h[node * 32 + lane] = make_uint2(*(unsigned*)&h0, *(unsigned*)&h1);
        }
    } else {
        const float2 as2 = ((const float2*)asrc)[lane];   // cols lane*2..+1
        const float2 ad2 = ((const float2*)adst)[lane];
        for (int r2 = 0; r2 < 16; r2++) {
            int node = base + m0 + r2;
            if (node >= n) break;
            float2 cv = *(float2*)&Cw[r2 * CPAD + lane * 2];
            float s = cv.x * as2.x + cv.y * as2.y;
            float d = cv.x * ad2.x + cv.y * ad2.y;
#pragma unroll
            for (int o = 1; o < 32; o <<= 1) {
                s += __shfl_xor_sync(0xffffffffu, s, o);
                d += __shfl_xor_sync(0xffffffffu, d, o);
            }
            if (lane == 0) {
                g_as2[node] = s;
                g_ad2[node] = d;
            }
            __half2 h = __float22half2_rn(cv);
            ((unsigned*)g_h2h)[node * 32 + lane] = *(unsigned*)&h;
        }
    }
}

__device__ __forceinline__ float att_w(float e) {
    float lr = (e > 0.f) ? e : 0.2f * e;
    return __expf(lr);
}

// ---------------- fused gather layer 1 (fp16): softmax-agg + bias + ELU -> fp16 x2 ----
__global__ void k_gather1(const float* __restrict__ b1, int n) {
    int node = (blockIdx.x * blockDim.x + threadIdx.x) >> 5;
    int lane = threadIdx.x & 31;
    if (node >= n) return;
    int head = lane >> 3;

    float ad = g_ad1[node * 4 + head];

    float w = att_w(g_as1[node * 4 + head] + ad);
    uint2 p = g_h1h[node * 32 + lane];
    float2 f0 = __half22float2(*(const __half2*)&p.x);
    float2 f1 = __half22float2(*(const __half2*)&p.y);
    float4 acc = make_float4(w * f0.x, w * f0.y, w * f1.x, w * f1.y);
    float wsum = w;

    int i = g_off[node];
    int iend = g_off[node + 1];
    for (; i < iend; i++) {
        int src = g_csr[i];
        float ww = att_w(g_as1[src * 4 + head] + ad);
        uint2 q = g_h1h[src * 32 + lane];
        float2 v0 = __half22float2(*(const __half2*)&q.x);
        float2 v1 = __half22float2(*(const __half2*)&q.y);
        acc.x += ww * v0.x;
        acc.y += ww * v0.y;
        acc.z += ww * v1.x;
        acc.w += ww * v1.y;
        wsum += ww;
    }
    float inv = 1.f / wsum;
    float4 bb = ((const float4*)b1)[lane];
    float ox = acc.x * inv + bb.x;
    float oy = acc.y * inv + bb.y;
    float oz = acc.z * inv + bb.z;
    float ow = acc.w * inv + bb.w;
    ox = (ox > 0.f) ? ox : expm1f(ox);
    oy = (oy > 0.f) ? oy : expm1f(oy);
    oz = (oz > 0.f) ? oz : expm1f(oz);
    ow = (ow > 0.f) ? ow : expm1f(ow);
    __half2 h0 = __float22half2_rn(make_float2(ox, oy));
    __half2 h1 = __float22half2_rn(make_float2(oz, ow));
    g_x2h[node * 32 + lane] = make_uint2(*(unsigned*)&h0, *(unsigned*)&h1);
}

// ---------------- fused gather layer 2 (fp16): softmax-agg + bias ----------------
__global__ void k_gather2(const float* __restrict__ b2, float* __restrict__ out, int n) {
    int node = (blockIdx.x * blockDim.x + threadIdx.x) >> 5;
    int lane = threadIdx.x & 31;
    if (node >= n) return;

    const __half2* H2 = (const __half2*)g_h2h;
    float ad = g_ad2[node];

    float w = att_w(g_as2[node] + ad);
    float2 hv = __half22float2(H2[node * 32 + lane]);
    float2 acc = make_float2(w * hv.x, w * hv.y);
    float wsum = w;

    int i = g_off[node];
    int iend = g_off[node + 1];
    for (; i < iend; i++) {
        int src = g_csr[i];
        float ww = att_w(g_as2[src] + ad);
        float2 v = __half22float2(H2[src * 32 + lane]);
        acc.x += ww * v.x;
        acc.y += ww * v.y;
        wsum += ww;
    }
    float inv = 1.f / wsum;
    float2 bb = ((const float2*)b2)[lane];
    ((float2*)out)[node * 32 + lane] =
        make_float2(acc.x * inv + bb.x, acc.y * inv + bb.y);
}

// ---------------- launch ----------------
extern "C" void kernel_launch(void* const* d_in, const int* in_sizes, int n_in,
                              void* d_out, int out_size) {
    const void* xidx = d_in[0];
    const void* ei = d_in[1];
    const float* emb = (const float*)d_in[2];
    const float* W1 = (const float*)d_in[3];
    const float* a_src1 = (const float*)d_in[4];
    const float* a_dst1 = (const float*)d_in[5];
    const float* b1 = (const float*)d_in[6];
    const float* W2 = (const float*)d_in[7];
    const float* a_src2 = (const float*)d_in[8];
    const float* a_dst2 = (const float*)d_in[9];
    const float* b2 = (const float*)d_in[10];
    float* out = (float*)d_out;

    int n = in_sizes[0];
    int e = in_sizes[1] / 2;

    int nb256 = (n + 255) / 256;
    int eb256 = (e + 255) / 256;
    int nwarp = (n + 7) / 8;
    int gb = (n + 63) / 64;
    int eb128 = (e + 127) / 128;

    k_conv_idx<<<nb256, 256>>>(xidx, W1, W2, n);
    k_conv_ei<<<eb256, 256>>>(ei, xidx, e);
    k_scan<<<nb256, 256>>>(n, e);

    k_gemm<1><<<gb + eb128, 128>>>(emb, a_src1, a_dst1, n, gb, e);
    k_gather1<<<nwarp, 256>>>(b1, n);

    k_gemm<2><<<gb, 128>>>(nullptr, a_src2, a_dst2, n, gb, 0);
    k_gather2<<<nwarp, 256>>>(b2, out, n);
}

// round 10
// speedup vs baseline: 1.3681x; 1.0463x over previous
#include <cuda_runtime.h>
#include <cuda_bf16.h>
#include <cuda_fp16.h>
#include <math.h>

#define MAXN 100000
#define MAXE 1600000

// ---------------- device scratch ----------------
__device__ uint2  g_h1h[MAXN * 32];   // layer1 features, fp16x4 per uint2 (128/node)
__device__ uint2  g_x2h[MAXN * 32];   // layer1 output (fp16), layer2 GEMM input
__device__ uint2  g_h2h[MAXN * 16];   // layer2 pre-agg features, fp16x4 (64/node)
__device__ __align__(16) __half g_w1t[128 * 128];  // W1^T fp16 (n-major)
__device__ __align__(16) __half g_w2t[64 * 128];   // W2^T fp16 (n-major)
__device__ float g_as1[MAXN * 4];
__device__ float g_ad1[MAXN * 4];
__device__ float g_as2[MAXN];
__device__ float g_ad2[MAXN];
__device__ int   g_xi[MAXN];
__device__ int   g_srcb[MAXE];
__device__ int   g_dstb[MAXE];
__device__ int   g_deg[MAXN];
__device__ int   g_off[MAXN + 1];
__device__ int   g_cur[MAXN];
__device__ int   g_csr[MAXE];
__device__ unsigned long long g_lb[512];

__device__ __forceinline__ bool sniff64(const int* xw) { return xw[1] == 0; }

// 16B-chunk swizzle: row-local XOR keeps ldmatrix column reads conflict-free.
__device__ __forceinline__ int swz(int row, int ch) {
    return (row * 16 + (ch ^ (row & 15))) << 4;   // byte offset
}

__device__ __forceinline__ void ldsm4(unsigned& r0, unsigned& r1,
                                      unsigned& r2, unsigned& r3, unsigned addr) {
    asm volatile("ldmatrix.sync.aligned.m8n8.x4.shared.b16 {%0,%1,%2,%3}, [%4];"
                 : "=r"(r0), "=r"(r1), "=r"(r2), "=r"(r3) : "r"(addr));
}
__device__ __forceinline__ void mma16816(float* c, unsigned a0, unsigned a1,
                                         unsigned a2, unsigned a3,
                                         unsigned b0, unsigned b1) {
    asm volatile(
        "mma.sync.aligned.m16n8k16.row.col.f32.f16.f16.f32 "
        "{%0,%1,%2,%3}, {%4,%5,%6,%7}, {%8,%9}, {%0,%1,%2,%3};"
        : "+f"(c[0]), "+f"(c[1]), "+f"(c[2]), "+f"(c[3])
        : "r"(a0), "r"(a1), "r"(a2), "r"(a3), "r"(b0), "r"(b1));
}

// ---------------- index normalization + W transpose/convert + lb reset ----------------
__global__ void k_conv_idx(const void* __restrict__ xidx,
                           const float* __restrict__ W1,
                           const float* __restrict__ W2, int n) {
    int i = blockIdx.x * blockDim.x + threadIdx.x;
    if (i < 512) g_lb[i] = 0ull;
    if (i < 128 * 128) {
        int nn = i >> 7, k = i & 127;
        g_w1t[i] = __float2half(W1[k * 128 + nn]);
    }
    if (i < 64 * 128) {
        int nn = i >> 7, k = i & 127;
        g_w2t[i] = __float2half(W2[k * 64 + nn]);
    }
    if (i >= n) return;
    bool is64 = sniff64((const int*)xidx);
    g_xi[i] = is64 ? (int)((const long long*)xidx)[i] : ((const int*)xidx)[i];
    g_deg[i] = 0;
}

__global__ void k_conv_ei(const void* __restrict__ ei,
                          const void* __restrict__ xidx, int e) {
    int i = blockIdx.x * blockDim.x + threadIdx.x;
    if (i >= e) return;
    bool is64 = sniff64((const int*)xidx);
    int s, d;
    if (is64) {
        s = (int)((const long long*)ei)[i];
        d = (int)((const long long*)ei)[(long long)e + i];
    } else {
        s = ((const int*)ei)[i];
        d = ((const int*)ei)[e + i];
    }
    g_srcb[i] = s;
    g_dstb[i] = d;
    atomicAdd(&g_deg[d], 1);
}

// ---------------- single-pass scan, warp-parallel decoupled lookback ----------------
__global__ void k_scan(int n, int etot) {
    __shared__ int s[256];
    __shared__ int s_prefix;
    int tid = threadIdx.x;
    int b = blockIdx.x;
    int i = b * 256 + tid;
    int v = (i < n) ? g_deg[i] : 0;
    s[tid] = v;
    __syncthreads();
    for (int o = 1; o < 256; o <<= 1) {
        int t = 0;
        if (tid >= o) t = s[tid - o];
        __syncthreads();
        s[tid] += t;
        __syncthreads();
    }
    int incl = s[tid];
    int agg = s[255];

    if (tid < 32) {
        if (tid == 0) {
            unsigned long long pub = (b == 0)
                ? ((2ull << 32) | (unsigned)agg)
                : ((1ull << 32) | (unsigned)agg);
            __threadfence();
            atomicExch(&g_lb[b], pub);
        }
        int ex = 0;
        if (b > 0) {
            int p = b - 1;
            while (true) {
                int idx = p - (int)tid;
                unsigned long long st = (idx >= 0) ? atomicAdd(&g_lb[idx], 0ull)
                                                   : (2ull << 32);
                unsigned flag = (unsigned)(st >> 32);
                if (__any_sync(0xffffffffu, flag == 0u)) continue;
                unsigned m2 = __ballot_sync(0xffffffffu, flag == 2u);
                int contrib;
                if (m2) {
                    int L = __ffs(m2) - 1;
                    contrib = ((int)tid <= L) ? (int)(unsigned)st : 0;
                } else {
                    contrib = (int)(unsigned)st;
                }
#pragma unroll
                for (int o = 16; o > 0; o >>= 1)
                    contrib += __shfl_xor_sync(0xffffffffu, contrib, o);
                ex += contrib;
                if (m2) break;
                p -= 32;
            }
            if (tid == 0) {
                __threadfence();
                atomicExch(&g_lb[b], (2ull << 32) | (unsigned)(ex + agg));
            }
        }
        if (tid == 0) s_prefix = ex;
    }
    __syncthreads();
    int ex = s_prefix;
    if (i < n) {
        int o = ex + incl - v;
        g_off[i] = o;
        g_cur[i] = o;
        if (i == n - 1) g_off[n] = etot;
    }
}

// ---------------- tensor-core GEMM, 8 warps, split-N + fused epilogue/scatter -------
// Block = 64 nodes, 256 threads. Warp = m16 x nCOLS/2 tile.
template <int LAYER>
__global__ void __launch_bounds__(256, 3) k_gemm(const float* __restrict__ Xin,
                                                 const float* __restrict__ asrc,
                                                 const float* __restrict__ adst,
                                                 int n, int gb, int e) {
    if (LAYER == 1 && (int)blockIdx.x >= gb) {
        int start = (blockIdx.x - gb) * 1024 + threadIdx.x;
#pragma unroll
        for (int k = 0; k < 4; k++) {
            int i = start + k * 256;
            if (i < e) {
                int pos = atomicAdd(&g_cur[g_dstb[i]], 1);
                g_csr[pos] = g_srcb[i];
            }
        }
        return;
    }

    constexpr int COLS = (LAYER == 1) ? 128 : 64;
    constexpr int NT2 = COLS / 16;          // n-tiles per warp (half of COLS/8): 8 / 4
    constexpr int CPAD = COLS + 4;
    constexpr int SBYTES = (LAYER == 1) ? (16384 + 32768) : (16384 + 16384);

    __shared__ __align__(16) char sbuf[SBYTES];
    char* Ab = sbuf;
    char* Bb = sbuf + 16384;

    const int tid = threadIdx.x;
    const int lane = tid & 31;
    const int wid = tid >> 5;
    const int base = blockIdx.x * 64;

    // ---- stage A (64 nodes x 128 k, fp16, swizzled) ----
    if (LAYER == 1) {
        const float4* E4 = (const float4*)Xin;
        for (int idx = tid; idx < 64 * 16; idx += 256) {
            int r = idx >> 4, ch = idx & 15;
            int node = base + r;
            uint4 val = make_uint4(0, 0, 0, 0);
            if (node < n) {
                long long g = g_xi[node];
                float4 x0 = E4[g * 32 + ch * 2];
                float4 x1 = E4[g * 32 + ch * 2 + 1];
                __half2 h0 = __float22half2_rn(make_float2(x0.x, x0.y));
                __half2 h1 = __float22half2_rn(make_float2(x0.z, x0.w));
                __half2 h2 = __float22half2_rn(make_float2(x1.x, x1.y));
                __half2 h3 = __float22half2_rn(make_float2(x1.z, x1.w));
                val.x = *(unsigned*)&h0;
                val.y = *(unsigned*)&h1;
                val.z = *(unsigned*)&h2;
                val.w = *(unsigned*)&h3;
            }
            *(uint4*)(Ab + swz(r, ch)) = val;
        }
    } else {
        for (int idx = tid; idx < 64 * 16; idx += 256) {
            int r = idx >> 4, ch = idx & 15;
            int node = base + r;
            uint4 val = make_uint4(0, 0, 0, 0);
            if (node < n) {
                uint2 v0 = g_x2h[node * 32 + ch * 2];
                uint2 v1 = g_x2h[node * 32 + ch * 2 + 1];
                val = make_uint4(v0.x, v0.y, v1.x, v1.y);
            }
            *(uint4*)(Ab + swz(r, ch)) = val;
        }
    }
    // ---- stage B = W^T (COLS n-rows x 128 k, fp16, swizzled) ----
    {
        const uint4* Wt = (const uint4*)((LAYER == 1) ? g_w1t : g_w2t);
        for (int idx = tid; idx < COLS * 16; idx += 256) {
            int r = idx >> 4, ch = idx & 15;
            *(uint4*)(Bb + swz(r, ch)) = Wt[r * 16 + ch];
        }
    }
    __syncthreads();

    // ---- mma mainloop: warp = m16 (mw) x n-half (nh) ----
    const int mw = wid >> 1;
    const int nh = wid & 1;
    const int m0 = mw * 16;

    float c[NT2][4];
#pragma unroll
    for (int j = 0; j < NT2; j++)
#pragma unroll
        for (int q = 0; q < 4; q++) c[j][q] = 0.f;

    const int tl = lane >> 3;
    const int rr = lane & 7;
    unsigned a_u = (unsigned)__cvta_generic_to_shared(Ab);
    unsigned b_u = (unsigned)__cvta_generic_to_shared(Bb);

#pragma unroll
    for (int s = 0; s < 8; s++) {
        int chunk = 2 * s + (tl >> 1);
        unsigned a0, a1, a2, a3;
        ldsm4(a0, a1, a2, a3, a_u + swz(m0 + (tl & 1) * 8 + rr, chunk));
#pragma unroll
        for (int t = 0; t < NT2 / 2; t++) {
            int brow = nh * (NT2 * 8) + t * 16;
            unsigned r0, r1, r2, r3;
            ldsm4(r0, r1, r2, r3, b_u + swz(brow + (tl & 1) * 8 + rr, chunk));
            mma16816(c[2 * t], a0, a1, a2, a3, r0, r2);
            mma16816(c[2 * t + 1], a0, a1, a2, a3, r1, r3);
        }
    }

    // ---- epilogue: frags -> smem (overlay), then row-wise logit reduce + fp16 store --
    __syncthreads();
    float* Cb = (float*)sbuf;
    {
        int g = lane >> 2, tg = lane & 3;
        int colbase = nh * (NT2 * 8);
#pragma unroll
        for (int j = 0; j < NT2; j++) {
            *(float2*)&Cb[(m0 + g) * CPAD + colbase + j * 8 + 2 * tg] =
                make_float2(c[j][0], c[j][1]);
            *(float2*)&Cb[(m0 + g + 8) * CPAD + colbase + j * 8 + 2 * tg] =
                make_float2(c[j][2], c[j][3]);
        }
    }
    __syncthreads();

    if (LAYER == 1) {
        const float4 as4 = ((const float4*)asrc)[lane];
        const float4 ad4 = ((const float4*)adst)[lane];
#pragma unroll
        for (int r2 = 0; r2 < 8; r2++) {
            int row = wid * 8 + r2;
            int node = base + row;
            if (node >= n) break;
            float4 cv = *(float4*)&Cb[row * CPAD + lane * 4];
            float s = cv.x * as4.x + cv.y * as4.y + cv.z * as4.z + cv.w * as4.w;
            float d = cv.x * ad4.x + cv.y * ad4.y + cv.z * ad4.z + cv.w * ad4.w;
#pragma unroll
            for (int o = 1; o < 8; o <<= 1) {
                s += __shfl_xor_sync(0xffffffffu, s, o);
                d += __shfl_xor_sync(0xffffffffu, d, o);
            }
            if ((lane & 7) == 0) {
                g_as1[node * 4 + (lane >> 3)] = s;
                g_ad1[node * 4 + (lane >> 3)] = d;
            }
            __half2 h0 = __float22half2_rn(make_float2(cv.x, cv.y));
            __half2 h1 = __float22half2_rn(make_float2(cv.z, cv.w));
            g_h1h[node * 32 + lane] = make_uint2(*(unsigned*)&h0, *(unsigned*)&h1);
        }
    } else {
        const float2 as2 = ((const float2*)asrc)[lane];
        const float2 ad2 = ((const float2*)adst)[lane];
#pragma unroll
        for (int r2 = 0; r2 < 8; r2++) {
            int row = wid * 8 + r2;
            int node = base + row;
            if (node >= n) break;
            float2 cv = *(float2*)&Cb[row * CPAD + lane * 2];
            float s = cv.x * as2.x + cv.y * as2.y;
            float d = cv.x * ad2.x + cv.y * ad2.y;
#pragma unroll
            for (int o = 1; o < 32; o <<= 1) {
                s += __shfl_xor_sync(0xffffffffu, s, o);
                d += __shfl_xor_sync(0xffffffffu, d, o);
            }
            if (lane == 0) {
                g_as2[node] = s;
                g_ad2[node] = d;
            }
            __half2 h = __float22half2_rn(cv);
            ((unsigned*)g_h2h)[node * 32 + lane] = *(unsigned*)&h;
        }
    }
}

__device__ __forceinline__ float att_w(float e) {
    float lr = (e > 0.f) ? e : 0.2f * e;
    return __expf(lr);
}

// ---------------- fused gather layer 1 (fp16): softmax-agg + bias + ELU -> fp16 x2 ----
__global__ void k_gather1(const float* __restrict__ b1, int n) {
    int node = (blockIdx.x * blockDim.x + threadIdx.x) >> 5;
    int lane = threadIdx.x & 31;
    if (node >= n) return;
    int head = lane >> 3;

    float ad = g_ad1[node * 4 + head];

    float w = att_w(g_as1[node * 4 + head] + ad);
    uint2 p = g_h1h[node * 32 + lane];
    float2 f0 = __half22float2(*(const __half2*)&p.x);
    float2 f1 = __half22float2(*(const __half2*)&p.y);
    float4 acc = make_float4(w * f0.x, w * f0.y, w * f1.x, w * f1.y);
    float wsum = w;

    int i = g_off[node];
    int iend = g_off[node + 1];
    for (; i < iend; i++) {
        int src = g_csr[i];
        float ww = att_w(g_as1[src * 4 + head] + ad);
        uint2 q = g_h1h[src * 32 + lane];
        float2 v0 = __half22float2(*(const __half2*)&q.x);
        float2 v1 = __half22float2(*(const __half2*)&q.y);
        acc.x += ww * v0.x;
        acc.y += ww * v0.y;
        acc.z += ww * v1.x;
        acc.w += ww * v1.y;
        wsum += ww;
    }
    float inv = 1.f / wsum;
    float4 bb = ((const float4*)b1)[lane];
    float ox = acc.x * inv + bb.x;
    float oy = acc.y * inv + bb.y;
    float oz = acc.z * inv + bb.z;
    float ow = acc.w * inv + bb.w;
    ox = (ox > 0.f) ? ox : expm1f(ox);
    oy = (oy > 0.f) ? oy : expm1f(oy);
    oz = (oz > 0.f) ? oz : expm1f(oz);
    ow = (ow > 0.f) ? ow : expm1f(ow);
    __half2 h0 = __float22half2_rn(make_float2(ox, oy));
    __half2 h1 = __float22half2_rn(make_float2(oz, ow));
    g_x2h[node * 32 + lane] = make_uint2(*(unsigned*)&h0, *(unsigned*)&h1);
}

// ---------------- fused gather layer 2 (fp16): softmax-agg + bias ----------------
__global__ void k_gather2(const float* __restrict__ b2, float* __restrict__ out, int n) {
    int node = (blockIdx.x * blockDim.x + threadIdx.x) >> 5;
    int lane = threadIdx.x & 31;
    if (node >= n) return;

    const __half2* H2 = (const __half2*)g_h2h;
    float ad = g_ad2[node];

    float w = att_w(g_as2[node] + ad);
    float2 hv = __half22float2(H2[node * 32 + lane]);
    float2 acc = make_float2(w * hv.x, w * hv.y);
    float wsum = w;

    int i = g_off[node];
    int iend = g_off[node + 1];
    for (; i < iend; i++) {
        int src = g_csr[i];
        float ww = att_w(g_as2[src] + ad);
        float2 v = __half22float2(H2[src * 32 + lane]);
        acc.x += ww * v.x;
        acc.y += ww * v.y;
        wsum += ww;
    }
    float inv = 1.f / wsum;
    float2 bb = ((const float2*)b2)[lane];
    ((float2*)out)[node * 32 + lane] =
        make_float2(acc.x * inv + bb.x, acc.y * inv + bb.y);
}

// ---------------- launch ----------------
extern "C" void kernel_launch(void* const* d_in, const int* in_sizes, int n_in,
                              void* d_out, int out_size) {
    const void* xidx = d_in[0];
    const void* ei = d_in[1];
    const float* emb = (const float*)d_in[2];
    const float* W1 = (const float*)d_in[3];
    const float* a_src1 = (const float*)d_in[4];
    const float* a_dst1 = (const float*)d_in[5];
    const float* b1 = (const float*)d_in[6];
    const float* W2 = (const float*)d_in[7];
    const float* a_src2 = (const float*)d_in[8];
    const float* a_dst2 = (const float*)d_in[9];
    const float* b2 = (const float*)d_in[10];
    float* out = (float*)d_out;

    int n = in_sizes[0];
    int e = in_sizes[1] / 2;

    int nb256 = (n + 255) / 256;
    int eb256 = (e + 255) / 256;
    int nwarp = (n + 7) / 8;
    int gb = (n + 63) / 64;
    int sb = (e + 1023) / 1024;   // scatter blocks: 256 thr x 4 edges

    k_conv_idx<<<nb256, 256>>>(xidx, W1, W2, n);
    k_conv_ei<<<eb256, 256>>>(ei, xidx, e);
    k_scan<<<nb256, 256>>>(n, e);

    k_gemm<1><<<gb + sb, 256>>>(emb, a_src1, a_dst1, n, gb, e);
    k_gather1<<<nwarp, 256>>>(b1, n);

    k_gemm<2><<<gb, 256>>>(nullptr, a_src2, a_dst2, n, gb, 0);
    k_gather2<<<nwarp, 256>>>(b2, out, n);
}

// round 11
// speedup vs baseline: 1.4146x; 1.0340x over previous
#include <cuda_runtime.h>
#include <cuda_bf16.h>
#include <cuda_fp16.h>
#include <math.h>

#define MAXN 100000
#define MAXE 1600000

// ---------------- device scratch ----------------
__device__ uint2  g_embh[MAXN * 32];  // gathered emb rows, fp16 (128/node)
__device__ uint2  g_h1h[MAXN * 32];   // layer1 features, fp16x4 per uint2 (128/node)
__device__ uint2  g_x2h[MAXN * 32];   // layer1 output (fp16), layer2 GEMM input
__device__ uint2  g_h2h[MAXN * 16];   // layer2 pre-agg features, fp16x4 (64/node)
__device__ __align__(16) __half g_w1t[128 * 128];  // W1^T fp16 (n-major)
__device__ __align__(16) __half g_w2t[64 * 128];   // W2^T fp16 (n-major)
__device__ float g_as1[MAXN * 4];
__device__ float g_ad1[MAXN * 4];
__device__ float g_as2[MAXN];
__device__ float g_ad2[MAXN];
__device__ int   g_srcb[MAXE];
__device__ int   g_dstb[MAXE];
__device__ int   g_deg[MAXN];
__device__ int   g_off[MAXN + 1];
__device__ int   g_cur[MAXN];
__device__ int   g_csr[MAXE];
__device__ unsigned long long g_lb[512];

__device__ __forceinline__ bool sniff64(const int* xw) { return xw[1] == 0; }

// 16B-chunk swizzle: row-local XOR keeps ldmatrix column reads conflict-free.
__device__ __forceinline__ int swz(int row, int ch) {
    return (row * 16 + (ch ^ (row & 15))) << 4;   // byte offset
}

__device__ __forceinline__ void ldsm4(unsigned& r0, unsigned& r1,
                                      unsigned& r2, unsigned& r3, unsigned addr) {
    asm volatile("ldmatrix.sync.aligned.m8n8.x4.shared.b16 {%0,%1,%2,%3}, [%4];"
                 : "=r"(r0), "=r"(r1), "=r"(r2), "=r"(r3) : "r"(addr));
}
__device__ __forceinline__ void mma16816(float* c, unsigned a0, unsigned a1,
                                         unsigned a2, unsigned a3,
                                         unsigned b0, unsigned b1) {
    asm volatile(
        "mma.sync.aligned.m16n8k16.row.col.f32.f16.f16.f32 "
        "{%0,%1,%2,%3}, {%4,%5,%6,%7}, {%8,%9}, {%0,%1,%2,%3};"
        : "+f"(c[0]), "+f"(c[1]), "+f"(c[2]), "+f"(c[3])
        : "r"(a0), "r"(a1), "r"(a2), "r"(a3), "r"(b0), "r"(b1));
}
__device__ __forceinline__ void cpa16(unsigned dst, const void* src) {
    asm volatile("cp.async.cg.shared.global [%0], [%1], 16;"
                 :: "r"(dst), "l"(src));
}
__device__ __forceinline__ void cpa_wait() {
    asm volatile("cp.async.commit_group;");
    asm volatile("cp.async.wait_group 0;" ::: "memory");
}

// ------- index/weight conversion + lb reset + emb gather->fp16 (tail blocks) -------
__global__ void k_conv_idx(const void* __restrict__ xidx,
                           const float* __restrict__ W1,
                           const float* __restrict__ W2,
                           const float* __restrict__ emb, int n, int nb) {
    if ((int)blockIdx.x >= nb) {
        // warp per node: gather emb row via x_indices, convert to fp16
        int node = (blockIdx.x - nb) * 8 + (threadIdx.x >> 5);
        int lane = threadIdx.x & 31;
        if (node >= n) return;
        bool is64 = sniff64((const int*)xidx);
        long long g = is64 ? ((const long long*)xidx)[node]
                           : (long long)((const int*)xidx)[node];
        float4 x = ((const float4*)emb)[g * 32 + lane];
        __half2 h0 = __float22half2_rn(make_float2(x.x, x.y));
        __half2 h1 = __float22half2_rn(make_float2(x.z, x.w));
        g_embh[node * 32 + lane] = make_uint2(*(unsigned*)&h0, *(unsigned*)&h1);
        return;
    }
    int i = blockIdx.x * blockDim.x + threadIdx.x;
    if (i < 512) g_lb[i] = 0ull;
    if (i < 128 * 128) {
        int nn = i >> 7, k = i & 127;
        g_w1t[i] = __float2half(W1[k * 128 + nn]);
    }
    if (i < 64 * 128) {
        int nn = i >> 7, k = i & 127;
        g_w2t[i] = __float2half(W2[k * 64 + nn]);
    }
    if (i < n) g_deg[i] = 0;
}

__global__ void k_conv_ei(const void* __restrict__ ei,
                          const void* __restrict__ xidx, int e) {
    int i = blockIdx.x * blockDim.x + threadIdx.x;
    if (i >= e) return;
    bool is64 = sniff64((const int*)xidx);
    int s, d;
    if (is64) {
        s = (int)((const long long*)ei)[i];
        d = (int)((const long long*)ei)[(long long)e + i];
    } else {
        s = ((const int*)ei)[i];
        d = ((const int*)ei)[e + i];
    }
    g_srcb[i] = s;
    g_dstb[i] = d;
    atomicAdd(&g_deg[d], 1);
}

// ---------------- single-pass scan, warp-parallel decoupled lookback ----------------
__global__ void k_scan(int n, int etot) {
    __shared__ int s[256];
    __shared__ int s_prefix;
    int tid = threadIdx.x;
    int b = blockIdx.x;
    int i = b * 256 + tid;
    int v = (i < n) ? g_deg[i] : 0;
    s[tid] = v;
    __syncthreads();
    for (int o = 1; o < 256; o <<= 1) {
        int t = 0;
        if (tid >= o) t = s[tid - o];
        __syncthreads();
        s[tid] += t;
        __syncthreads();
    }
    int incl = s[tid];
    int agg = s[255];

    if (tid < 32) {
        if (tid == 0) {
            unsigned long long pub = (b == 0)
                ? ((2ull << 32) | (unsigned)agg)
                : ((1ull << 32) | (unsigned)agg);
            __threadfence();
            atomicExch(&g_lb[b], pub);
        }
        int ex = 0;
        if (b > 0) {
            int p = b - 1;
            while (true) {
                int idx = p - (int)tid;
                unsigned long long st = (idx >= 0) ? atomicAdd(&g_lb[idx], 0ull)
                                                   : (2ull << 32);
                unsigned flag = (unsigned)(st >> 32);
                if (__any_sync(0xffffffffu, flag == 0u)) continue;
                unsigned m2 = __ballot_sync(0xffffffffu, flag == 2u);
                int contrib;
                if (m2) {
                    int L = __ffs(m2) - 1;
                    contrib = ((int)tid <= L) ? (int)(unsigned)st : 0;
                } else {
                    contrib = (int)(unsigned)st;
                }
#pragma unroll
                for (int o = 16; o > 0; o >>= 1)
                    contrib += __shfl_xor_sync(0xffffffffu, contrib, o);
                ex += contrib;
                if (m2) break;
                p -= 32;
            }
            if (tid == 0) {
                __threadfence();
                atomicExch(&g_lb[b], (2ull << 32) | (unsigned)(ex + agg));
            }
        }
        if (tid == 0) s_prefix = ex;
    }
    __syncthreads();
    int ex = s_prefix;
    if (i < n) {
        int o = ex + incl - v;
        g_off[i] = o;
        g_cur[i] = o;
        if (i == n - 1) g_off[n] = etot;
    }
}

// ---------------- tensor-core GEMM, cp.async staging, 8 warps split-N -------------
// Block = 64 nodes, 256 threads. Warp = m16 x nCOLS/2 tile. K = 128. A source fp16.
template <int LAYER>
__global__ void __launch_bounds__(256, 4) k_gemm(const float* __restrict__ asrc,
                                                 const float* __restrict__ adst,
                                                 int n, int gb, int e) {
    if (LAYER == 1 && (int)blockIdx.x >= gb) {
        int start = (blockIdx.x - gb) * 1024 + threadIdx.x;
#pragma unroll
        for (int k = 0; k < 4; k++) {
            int i = start + k * 256;
            if (i < e) {
                int pos = atomicAdd(&g_cur[g_dstb[i]], 1);
                g_csr[pos] = g_srcb[i];
            }
        }
        return;
    }

    constexpr int COLS = (LAYER == 1) ? 128 : 64;
    constexpr int NT2 = COLS / 16;          // n-tiles per warp: 8 / 4
    constexpr int CPAD = COLS + 4;
    constexpr int SBYTES = (LAYER == 1) ? (16384 + 32768) : (16384 + 16384);

    __shared__ __align__(16) char sbuf[SBYTES];
    char* Ab = sbuf;
    char* Bb = sbuf + 16384;

    const int tid = threadIdx.x;
    const int lane = tid & 31;
    const int wid = tid >> 5;
    const int base = blockIdx.x * 64;

    unsigned a_u = (unsigned)__cvta_generic_to_shared(Ab);
    unsigned b_u = (unsigned)__cvta_generic_to_shared(Bb);

    // ---- stage A (fp16 node rows, cp.async) ----
    const uint2* Asrc = (LAYER == 1) ? g_embh : g_x2h;
#pragma unroll 4
    for (int idx = tid; idx < 64 * 16; idx += 256) {
        int r = idx >> 4, ch = idx & 15;
        int node = base + r;
        if (node < n) cpa16(a_u + swz(r, ch), Asrc + node * 32 + ch * 2);
        else *(uint4*)(Ab + swz(r, ch)) = make_uint4(0, 0, 0, 0);
    }
    // ---- stage B = W^T (cp.async) ----
    {
        const uint4* Wt = (const uint4*)((LAYER == 1) ? g_w1t : g_w2t);
#pragma unroll 4
        for (int idx = tid; idx < COLS * 16; idx += 256) {
            int r = idx >> 4, ch = idx & 15;
            cpa16(b_u + swz(r, ch), Wt + r * 16 + ch);
        }
    }
    cpa_wait();
    __syncthreads();

    // ---- mma mainloop: warp = m16 (mw) x n-half (nh) ----
    const int mw = wid >> 1;
    const int nh = wid & 1;
    const int m0 = mw * 16;

    float c[NT2][4];
#pragma unroll
    for (int j = 0; j < NT2; j++)
#pragma unroll
        for (int q = 0; q < 4; q++) c[j][q] = 0.f;

    const int tl = lane >> 3;
    const int rr = lane & 7;

#pragma unroll
    for (int s = 0; s < 8; s++) {
        int chunk = 2 * s + (tl >> 1);
        unsigned a0, a1, a2, a3;
        ldsm4(a0, a1, a2, a3, a_u + swz(m0 + (tl & 1) * 8 + rr, chunk));
#pragma unroll
        for (int t = 0; t < NT2 / 2; t++) {
            int brow = nh * (NT2 * 8) + t * 16;
            unsigned r0, r1, r2, r3;
            ldsm4(r0, r1, r2, r3, b_u + swz(brow + (tl & 1) * 8 + rr, chunk));
            mma16816(c[2 * t], a0, a1, a2, a3, r0, r2);
            mma16816(c[2 * t + 1], a0, a1, a2, a3, r1, r3);
        }
    }

    // ---- epilogue: frags -> smem (overlay), row-wise logit reduce + fp16 store ----
    __syncthreads();
    float* Cb = (float*)sbuf;
    {
        int g = lane >> 2, tg = lane & 3;
        int colbase = nh * (NT2 * 8);
#pragma unroll
        for (int j = 0; j < NT2; j++) {
            *(float2*)&Cb[(m0 + g) * CPAD + colbase + j * 8 + 2 * tg] =
                make_float2(c[j][0], c[j][1]);
            *(float2*)&Cb[(m0 + g + 8) * CPAD + colbase + j * 8 + 2 * tg] =
                make_float2(c[j][2], c[j][3]);
        }
    }
    __syncthreads();

    if (LAYER == 1) {
        const float4 as4 = ((const float4*)asrc)[lane];
        const float4 ad4 = ((const float4*)adst)[lane];
#pragma unroll
        for (int r2 = 0; r2 < 8; r2++) {
            int row = wid * 8 + r2;
            int node = base + row;
            if (node >= n) break;
            float4 cv = *(float4*)&Cb[row * CPAD + lane * 4];
            float s = cv.x * as4.x + cv.y * as4.y + cv.z * as4.z + cv.w * as4.w;
            float d = cv.x * ad4.x + cv.y * ad4.y + cv.z * ad4.z + cv.w * ad4.w;
#pragma unroll
            for (int o = 1; o < 8; o <<= 1) {
                s += __shfl_xor_sync(0xffffffffu, s, o);
                d += __shfl_xor_sync(0xffffffffu, d, o);
            }
            if ((lane & 7) == 0) {
                g_as1[node * 4 + (lane >> 3)] = s;
                g_ad1[node * 4 + (lane >> 3)] = d;
            }
            __half2 h0 = __float22half2_rn(make_float2(cv.x, cv.y));
            __half2 h1 = __float22half2_rn(make_float2(cv.z, cv.w));
            g_h1h[node * 32 + lane] = make_uint2(*(unsigned*)&h0, *(unsigned*)&h1);
        }
    } else {
        const float2 as2 = ((const float2*)asrc)[lane];
        const float2 ad2 = ((const float2*)adst)[lane];
#pragma unroll
        for (int r2 = 0; r2 < 8; r2++) {
            int row = wid * 8 + r2;
            int node = base + row;
            if (node >= n) break;
            float2 cv = *(float2*)&Cb[row * CPAD + lane * 2];
            float s = cv.x * as2.x + cv.y * as2.y;
            float d = cv.x * ad2.x + cv.y * ad2.y;
#pragma unroll
            for (int o = 1; o < 32; o <<= 1) {
                s += __shfl_xor_sync(0xffffffffu, s, o);
                d += __shfl_xor_sync(0xffffffffu, d, o);
            }
            if (lane == 0) {
                g_as2[node] = s;
                g_ad2[node] = d;
            }
            __half2 h = __float22half2_rn(cv);
            ((unsigned*)g_h2h)[node * 32 + lane] = *(unsigned*)&h;
        }
    }
}

__device__ __forceinline__ float att_w(float e) {
    float lr = (e > 0.f) ? e : 0.2f * e;
    return __expf(lr);
}

// ---------------- fused gather layer 1 (fp16): softmax-agg + bias + ELU -> fp16 x2 ----
__global__ void k_gather1(const float* __restrict__ b1, int n) {
    int node = (blockIdx.x * blockDim.x + threadIdx.x) >> 5;
    int lane = threadIdx.x & 31;
    if (node >= n) return;
    int head = lane >> 3;

    float ad = g_ad1[node * 4 + head];

    float w = att_w(g_as1[node * 4 + head] + ad);
    uint2 p = g_h1h[node * 32 + lane];
    float2 f0 = __half22float2(*(const __half2*)&p.x);
    float2 f1 = __half22float2(*(const __half2*)&p.y);
    float4 acc = make_float4(w * f0.x, w * f0.y, w * f1.x, w * f1.y);
    float wsum = w;

    int i = g_off[node];
    int iend = g_off[node + 1];
    for (; i < iend; i++) {
        int src = g_csr[i];
        float ww = att_w(g_as1[src * 4 + head] + ad);
        uint2 q = g_h1h[src * 32 + lane];
        float2 v0 = __half22float2(*(const __half2*)&q.x);
        float2 v1 = __half22float2(*(const __half2*)&q.y);
        acc.x += ww * v0.x;
        acc.y += ww * v0.y;
        acc.z += ww * v1.x;
        acc.w += ww * v1.y;
        wsum += ww;
    }
    float inv = 1.f / wsum;
    float4 bb = ((const float4*)b1)[lane];
    float ox = acc.x * inv + bb.x;
    float oy = acc.y * inv + bb.y;
    float oz = acc.z * inv + bb.z;
    float ow = acc.w * inv + bb.w;
    ox = (ox > 0.f) ? ox : expm1f(ox);
    oy = (oy > 0.f) ? oy : expm1f(oy);
    oz = (oz > 0.f) ? oz : expm1f(oz);
    ow = (ow > 0.f) ? ow : expm1f(ow);
    __half2 h0 = __float22half2_rn(make_float2(ox, oy));
    __half2 h1 = __float22half2_rn(make_float2(oz, ow));
    g_x2h[node * 32 + lane] = make_uint2(*(unsigned*)&h0, *(unsigned*)&h1);
}

// ---------------- fused gather layer 2 (fp16): softmax-agg + bias ----------------
__global__ void k_gather2(const float* __restrict__ b2, float* __restrict__ out, int n) {
    int node = (blockIdx.x * blockDim.x + threadIdx.x) >> 5;
    int lane = threadIdx.x & 31;
    if (node >= n) return;

    const __half2* H2 = (const __half2*)g_h2h;
    float ad = g_ad2[node];

    float w = att_w(g_as2[node] + ad);
    float2 hv = __half22float2(H2[node * 32 + lane]);
    float2 acc = make_float2(w * hv.x, w * hv.y);
    float wsum = w;

    int i = g_off[node];
    int iend = g_off[node + 1];
    for (; i < iend; i++) {
        int src = g_csr[i];
        float ww = att_w(g_as2[src] + ad);
        float2 v = __half22float2(H2[src * 32 + lane]);
        acc.x += ww * v.x;
        acc.y += ww * v.y;
        wsum += ww;
    }
    float inv = 1.f / wsum;
    float2 bb = ((const float2*)b2)[lane];
    ((float2*)out)[node * 32 + lane] =
        make_float2(acc.x * inv + bb.x, acc.y * inv + bb.y);
}

// ---------------- launch ----------------
extern "C" void kernel_launch(void* const* d_in, const int* in_sizes, int n_in,
                              void* d_out, int out_size) {
    const void* xidx = d_in[0];
    const void* ei = d_in[1];
    const float* emb = (const float*)d_in[2];
    const float* W1 = (const float*)d_in[3];
    const float* a_src1 = (const float*)d_in[4];
    const float* a_dst1 = (const float*)d_in[5];
    const float* b1 = (const float*)d_in[6];
    const float* W2 = (const float*)d_in[7];
    const float* a_src2 = (const float*)d_in[8];
    const float* a_dst2 = (const float*)d_in[9];
    const float* b2 = (const float*)d_in[10];
    float* out = (float*)d_out;

    int n = in_sizes[0];
    int e = in_sizes[1] / 2;

    int nb256 = (n + 255) / 256;
    int eb256 = (e + 255) / 256;
    int nwarp = (n + 7) / 8;
    int gb = (n + 63) / 64;
    int sb = (e + 1023) / 1024;   // scatter blocks: 256 thr x 4 edges
    int cb = (n + 7) / 8;         // emb-convert blocks: 8 warps/block, warp/node

    k_conv_idx<<<nb256 + cb, 256>>>(xidx, W1, W2, emb, n, nb256);
    k_conv_ei<<<eb256, 256>>>(ei, xidx, e);
    k_scan<<<nb256, 256>>>(n, e);

    k_gemm<1><<<gb + sb, 256>>>(a_src1, a_dst1, n, gb, e);
    k_gather1<<<nwarp, 256>>>(b1, n);

    k_gemm<2><<<gb, 256>>>(a_src2, a_dst2, n, gb, 0);
    k_gather2<<<nwarp, 256>>>(b2, out, n);
}

// round 12
// speedup vs baseline: 1.4438x; 1.0206x over previous
#include <cuda_runtime.h>
#include <cuda_bf16.h>
#include <cuda_fp16.h>
#include <math.h>

#define MAXN 100000
#define MAXE 1600000

// ---------------- device scratch ----------------
__device__ uint2  g_embh[MAXN * 32];  // gathered emb rows, fp16 (128/node)
__device__ uint2  g_h1h[MAXN * 32];   // layer1 features, fp16x4 per uint2 (128/node)
__device__ uint2  g_x2h[MAXN * 32];   // layer1 output (fp16), layer2 GEMM input
__device__ uint2  g_h2h[MAXN * 16];   // layer2 pre-agg features, fp16x4 (64/node)
__device__ __align__(16) __half g_w1t[128 * 128];  // W1^T fp16 (n-major)
__device__ __align__(16) __half g_w2t[64 * 128];   // W2^T fp16 (n-major)
__device__ float g_as1[MAXN * 4];
__device__ float g_ad1[MAXN * 4];
__device__ float g_as2[MAXN];
__device__ float g_ad2[MAXN];
__device__ int   g_srcb[MAXE];
__device__ int   g_dstb[MAXE];
__device__ int   g_deg[MAXN];
__device__ int   g_off[MAXN + 1];
__device__ int   g_cur[MAXN];
__device__ int   g_csr[MAXE];
__device__ unsigned long long g_lb[512];

__device__ __forceinline__ bool sniff64(const int* xw) { return xw[1] == 0; }

// 16B-chunk swizzle: row-local XOR keeps ldmatrix column reads conflict-free.
__device__ __forceinline__ int swz(int row, int ch) {
    return (row * 16 + (ch ^ (row & 15))) << 4;   // byte offset
}

__device__ __forceinline__ void ldsm4(unsigned& r0, unsigned& r1,
                                      unsigned& r2, unsigned& r3, unsigned addr) {
    asm volatile("ldmatrix.sync.aligned.m8n8.x4.shared.b16 {%0,%1,%2,%3}, [%4];"
                 : "=r"(r0), "=r"(r1), "=r"(r2), "=r"(r3) : "r"(addr));
}
__device__ __forceinline__ void mma16816(float* c, unsigned a0, unsigned a1,
                                         unsigned a2, unsigned a3,
                                         unsigned b0, unsigned b1) {
    asm volatile(
        "mma.sync.aligned.m16n8k16.row.col.f32.f16.f16.f32 "
        "{%0,%1,%2,%3}, {%4,%5,%6,%7}, {%8,%9}, {%0,%1,%2,%3};"
        : "+f"(c[0]), "+f"(c[1]), "+f"(c[2]), "+f"(c[3])
        : "r"(a0), "r"(a1), "r"(a2), "r"(a3), "r"(b0), "r"(b1));
}
__device__ __forceinline__ void cpa16(unsigned dst, const void* src) {
    asm volatile("cp.async.cg.shared.global [%0], [%1], 16;"
                 :: "r"(dst), "l"(src));
}
__device__ __forceinline__ void cpa_wait() {
    asm volatile("cp.async.commit_group;");
    asm volatile("cp.async.wait_group 0;" ::: "memory");
}

// ------- index/weight conversion + lb reset + emb gather->fp16 (tail blocks) -------
__global__ void k_conv_idx(const void* __restrict__ xidx,
                           const float* __restrict__ W1,
                           const float* __restrict__ W2,
                           const float* __restrict__ emb, int n, int nb) {
    if ((int)blockIdx.x >= nb) {
        // warp per node: gather emb row via x_indices, convert to fp16
        int node = (blockIdx.x - nb) * 8 + (threadIdx.x >> 5);
        int lane = threadIdx.x & 31;
        if (node >= n) return;
        bool is64 = sniff64((const int*)xidx);
        long long g = is64 ? ((const long long*)xidx)[node]
                           : (long long)((const int*)xidx)[node];
        float4 x = ((const float4*)emb)[g * 32 + lane];
        __half2 h0 = __float22half2_rn(make_float2(x.x, x.y));
        __half2 h1 = __float22half2_rn(make_float2(x.z, x.w));
        g_embh[node * 32 + lane] = make_uint2(*(unsigned*)&h0, *(unsigned*)&h1);
        return;
    }
    int i = blockIdx.x * blockDim.x + threadIdx.x;
    if (i < 512) g_lb[i] = 0ull;
    if (i < 128 * 128) {
        int nn = i >> 7, k = i & 127;
        g_w1t[i] = __float2half(W1[k * 128 + nn]);
    }
    if (i < 64 * 128) {
        int nn = i >> 7, k = i & 127;
        g_w2t[i] = __float2half(W2[k * 64 + nn]);
    }
    if (i < n) g_deg[i] = 0;
}

__global__ void k_conv_ei(const void* __restrict__ ei,
                          const void* __restrict__ xidx, int e) {
    int i = blockIdx.x * blockDim.x + threadIdx.x;
    if (i >= e) return;
    bool is64 = sniff64((const int*)xidx);
    int s, d;
    if (is64) {
        s = (int)((const long long*)ei)[i];
        d = (int)((const long long*)ei)[(long long)e + i];
    } else {
        s = ((const int*)ei)[i];
        d = ((const int*)ei)[e + i];
    }
    g_srcb[i] = s;
    g_dstb[i] = d;
    atomicAdd(&g_deg[d], 1);
}

// ---------------- single-pass scan, warp-parallel decoupled lookback ----------------
__global__ void k_scan(int n, int etot) {
    __shared__ int s[256];
    __shared__ int s_prefix;
    int tid = threadIdx.x;
    int b = blockIdx.x;
    int i = b * 256 + tid;
    int v = (i < n) ? g_deg[i] : 0;
    s[tid] = v;
    __syncthreads();
    for (int o = 1; o < 256; o <<= 1) {
        int t = 0;
        if (tid >= o) t = s[tid - o];
        __syncthreads();
        s[tid] += t;
        __syncthreads();
    }
    int incl = s[tid];
    int agg = s[255];

    if (tid < 32) {
        if (tid == 0) {
            unsigned long long pub = (b == 0)
                ? ((2ull << 32) | (unsigned)agg)
                : ((1ull << 32) | (unsigned)agg);
            __threadfence();
            atomicExch(&g_lb[b], pub);
        }
        int ex = 0;
        if (b > 0) {
            int p = b - 1;
            while (true) {
                int idx = p - (int)tid;
                unsigned long long st = (idx >= 0) ? atomicAdd(&g_lb[idx], 0ull)
                                                   : (2ull << 32);
                unsigned flag = (unsigned)(st >> 32);
                if (__any_sync(0xffffffffu, flag == 0u)) continue;
                unsigned m2 = __ballot_sync(0xffffffffu, flag == 2u);
                int contrib;
                if (m2) {
                    int L = __ffs(m2) - 1;
                    contrib = ((int)tid <= L) ? (int)(unsigned)st : 0;
                } else {
                    contrib = (int)(unsigned)st;
                }
#pragma unroll
                for (int o = 16; o > 0; o >>= 1)
                    contrib += __shfl_xor_sync(0xffffffffu, contrib, o);
                ex += contrib;
                if (m2) break;
                p -= 32;
            }
            if (tid == 0) {
                __threadfence();
                atomicExch(&g_lb[b], (2ull << 32) | (unsigned)(ex + agg));
            }
        }
        if (tid == 0) s_prefix = ex;
    }
    __syncthreads();
    int ex = s_prefix;
    if (i < n) {
        int o = ex + incl - v;
        g_off[i] = o;
        g_cur[i] = o;
        if (i == n - 1) g_off[n] = etot;
    }
}

// ---------------- tensor-core GEMM, cp.async staging, 8 warps split-N -------------
// Block = 64 nodes, 256 threads. Warp = m16 x nCOLS/2 tile. K = 128. A source fp16.
// LAYER 1: GEMM and CSR-scatter blocks INTERLEAVED (even/odd) so both roles
// coexist in every wave and the scatter's memory work hides under GEMM compute.
template <int LAYER>
__global__ void __launch_bounds__(256, 4) k_gemm(const float* __restrict__ asrc,
                                                 const float* __restrict__ adst,
                                                 int n, int gb, int sb, int e) {
    int gemm_idx = blockIdx.x;
    if (LAYER == 1) {
        int bid = blockIdx.x;
        int mn = (gb < sb) ? gb : sb;
        int both = 2 * mn;
        bool isc;
        int ridx;
        if (bid < both) {
            isc = (bid & 1);
            ridx = bid >> 1;
        } else if (gb >= sb) {
            isc = false;
            ridx = bid - both + mn;
        } else {
            isc = true;
            ridx = bid - both + mn;
        }
        if (isc) {
            int start = ridx * 1024 + threadIdx.x;
#pragma unroll
            for (int k = 0; k < 4; k++) {
                int i = start + k * 256;
                if (i < e) {
                    int pos = atomicAdd(&g_cur[g_dstb[i]], 1);
                    g_csr[pos] = g_srcb[i];
                }
            }
            return;
        }
        gemm_idx = ridx;
    }

    constexpr int COLS = (LAYER == 1) ? 128 : 64;
    constexpr int NT2 = COLS / 16;          // n-tiles per warp: 8 / 4
    constexpr int CPAD = COLS + 4;
    constexpr int SBYTES = (LAYER == 1) ? (16384 + 32768) : (16384 + 16384);

    __shared__ __align__(16) char sbuf[SBYTES];
    char* Ab = sbuf;
    char* Bb = sbuf + 16384;

    const int tid = threadIdx.x;
    const int lane = tid & 31;
    const int wid = tid >> 5;
    const int base = gemm_idx * 64;

    unsigned a_u = (unsigned)__cvta_generic_to_shared(Ab);
    unsigned b_u = (unsigned)__cvta_generic_to_shared(Bb);

    // ---- stage A (fp16 node rows, cp.async) ----
    const uint2* Asrc = (LAYER == 1) ? g_embh : g_x2h;
#pragma unroll 4
    for (int idx = tid; idx < 64 * 16; idx += 256) {
        int r = idx >> 4, ch = idx & 15;
        int node = base + r;
        if (node < n) cpa16(a_u + swz(r, ch), Asrc + node * 32 + ch * 2);
        else *(uint4*)(Ab + swz(r, ch)) = make_uint4(0, 0, 0, 0);
    }
    // ---- stage B = W^T (cp.async) ----
    {
        const uint4* Wt = (const uint4*)((LAYER == 1) ? g_w1t : g_w2t);
#pragma unroll 4
        for (int idx = tid; idx < COLS * 16; idx += 256) {
            int r = idx >> 4, ch = idx & 15;
            cpa16(b_u + swz(r, ch), Wt + r * 16 + ch);
        }
    }
    cpa_wait();
    __syncthreads();

    // ---- mma mainloop: warp = m16 (mw) x n-half (nh) ----
    const int mw = wid >> 1;
    const int nh = wid & 1;
    const int m0 = mw * 16;

    float c[NT2][4];
#pragma unroll
    for (int j = 0; j < NT2; j++)
#pragma unroll
        for (int q = 0; q < 4; q++) c[j][q] = 0.f;

    const int tl = lane >> 3;
    const int rr = lane & 7;

#pragma unroll
    for (int s = 0; s < 8; s++) {
        int chunk = 2 * s + (tl >> 1);
        unsigned a0, a1, a2, a3;
        ldsm4(a0, a1, a2, a3, a_u + swz(m0 + (tl & 1) * 8 + rr, chunk));
#pragma unroll
        for (int t = 0; t < NT2 / 2; t++) {
            int brow = nh * (NT2 * 8) + t * 16;
            unsigned r0, r1, r2, r3;
            ldsm4(r0, r1, r2, r3, b_u + swz(brow + (tl & 1) * 8 + rr, chunk));
            mma16816(c[2 * t], a0, a1, a2, a3, r0, r2);
            mma16816(c[2 * t + 1], a0, a1, a2, a3, r1, r3);
        }
    }

    // ---- epilogue: frags -> smem (overlay), row-wise logit reduce + fp16 store ----
    __syncthreads();
    float* Cb = (float*)sbuf;
    {
        int g = lane >> 2, tg = lane & 3;
        int colbase = nh * (NT2 * 8);
#pragma unroll
        for (int j = 0; j < NT2; j++) {
            *(float2*)&Cb[(m0 + g) * CPAD + colbase + j * 8 + 2 * tg] =
                make_float2(c[j][0], c[j][1]);
            *(float2*)&Cb[(m0 + g + 8) * CPAD + colbase + j * 8 + 2 * tg] =
                make_float2(c[j][2], c[j][3]);
        }
    }
    __syncthreads();

    if (LAYER == 1) {
        const float4 as4 = ((const float4*)asrc)[lane];
        const float4 ad4 = ((const float4*)adst)[lane];
#pragma unroll
        for (int r2 = 0; r2 < 8; r2++) {
            int row = wid * 8 + r2;
            int node = base + row;
            if (node >= n) break;
            float4 cv = *(float4*)&Cb[row * CPAD + lane * 4];
            float s = cv.x * as4.x + cv.y * as4.y + cv.z * as4.z + cv.w * as4.w;
            float d = cv.x * ad4.x + cv.y * ad4.y + cv.z * ad4.z + cv.w * ad4.w;
#pragma unroll
            for (int o = 1; o < 8; o <<= 1) {
                s += __shfl_xor_sync(0xffffffffu, s, o);
                d += __shfl_xor_sync(0xffffffffu, d, o);
            }
            if ((lane & 7) == 0) {
                g_as1[node * 4 + (lane >> 3)] = s;
                g_ad1[node * 4 + (lane >> 3)] = d;
            }
            __half2 h0 = __float22half2_rn(make_float2(cv.x, cv.y));
            __half2 h1 = __float22half2_rn(make_float2(cv.z, cv.w));
            g_h1h[node * 32 + lane] = make_uint2(*(unsigned*)&h0, *(unsigned*)&h1);
        }
    } else {
        const float2 as2 = ((const float2*)asrc)[lane];
        const float2 ad2 = ((const float2*)adst)[lane];
#pragma unroll
        for (int r2 = 0; r2 < 8; r2++) {
            int row = wid * 8 + r2;
            int node = base + row;
            if (node >= n) break;
            float2 cv = *(float2*)&Cb[row * CPAD + lane * 2];
            float s = cv.x * as2.x + cv.y * as2.y;
            float d = cv.x * ad2.x + cv.y * ad2.y;
#pragma unroll
            for (int o = 1; o < 32; o <<= 1) {
                s += __shfl_xor_sync(0xffffffffu, s, o);
                d += __shfl_xor_sync(0xffffffffu, d, o);
            }
            if (lane == 0) {
                g_as2[node] = s;
                g_ad2[node] = d;
            }
            __half2 h = __float22half2_rn(cv);
            ((unsigned*)g_h2h)[node * 32 + lane] = *(unsigned*)&h;
        }
    }
}

__device__ __forceinline__ float att_w(float e) {
    float lr = (e > 0.f) ? e : 0.2f * e;
    return __expf(lr);
}

// ---------------- fused gather layer 1 (fp16): softmax-agg + bias + ELU -> fp16 x2 ----
__global__ void k_gather1(const float* __restrict__ b1, int n) {
    int node = (blockIdx.x * blockDim.x + threadIdx.x) >> 5;
    int lane = threadIdx.x & 31;
    if (node >= n) return;
    int head = lane >> 3;

    float ad = g_ad1[node * 4 + head];

    float w = att_w(g_as1[node * 4 + head] + ad);
    uint2 p = g_h1h[node * 32 + lane];
    float2 f0 = __half22float2(*(const __half2*)&p.x);
    float2 f1 = __half22float2(*(const __half2*)&p.y);
    float4 acc = make_float4(w * f0.x, w * f0.y, w * f1.x, w * f1.y);
    float wsum = w;

    int i = g_off[node];
    int iend = g_off[node + 1];
    for (; i < iend; i++) {
        int src = g_csr[i];
        float ww = att_w(g_as1[src * 4 + head] + ad);
        uint2 q = g_h1h[src * 32 + lane];
        float2 v0 = __half22float2(*(const __half2*)&q.x);
        float2 v1 = __half22float2(*(const __half2*)&q.y);
        acc.x += ww * v0.x;
        acc.y += ww * v0.y;
        acc.z += ww * v1.x;
        acc.w += ww * v1.y;
        wsum += ww;
    }
    float inv = 1.f / wsum;
    float4 bb = ((const float4*)b1)[lane];
    float ox = acc.x * inv + bb.x;
    float oy = acc.y * inv + bb.y;
    float oz = acc.z * inv + bb.z;
    float ow = acc.w * inv + bb.w;
    ox = (ox > 0.f) ? ox : expm1f(ox);
    oy = (oy > 0.f) ? oy : expm1f(oy);
    oz = (oz > 0.f) ? oz : expm1f(oz);
    ow = (ow > 0.f) ? ow : expm1f(ow);
    __half2 h0 = __float22half2_rn(make_float2(ox, oy));
    __half2 h1 = __float22half2_rn(make_float2(oz, ow));
    g_x2h[node * 32 + lane] = make_uint2(*(unsigned*)&h0, *(unsigned*)&h1);
}

// ---------------- fused gather layer 2 (fp16): softmax-agg + bias ----------------
__global__ void k_gather2(const float* __restrict__ b2, float* __restrict__ out, int n) {
    int node = (blockIdx.x * blockDim.x + threadIdx.x) >> 5;
    int lane = threadIdx.x & 31;
    if (node >= n) return;

    const __half2* H2 = (const __half2*)g_h2h;
    float ad = g_ad2[node];

    float w = att_w(g_as2[node] + ad);
    float2 hv = __half22float2(H2[node * 32 + lane]);
    float2 acc = make_float2(w * hv.x, w * hv.y);
    float wsum = w;

    int i = g_off[node];
    int iend = g_off[node + 1];
    for (; i < iend; i++) {
        int src = g_csr[i];
        float ww = att_w(g_as2[src] + ad);
        float2 v = __half22float2(H2[src * 32 + lane]);
        acc.x += ww * v.x;
        acc.y += ww * v.y;
        wsum += ww;
    }
    float inv = 1.f / wsum;
    float2 bb = ((const float2*)b2)[lane];
    ((float2*)out)[node * 32 + lane] =
        make_float2(acc.x * inv + bb.x, acc.y * inv + bb.y);
}

// ---------------- launch ----------------
extern "C" void kernel_launch(void* const* d_in, const int* in_sizes, int n_in,
                              void* d_out, int out_size) {
    const void* xidx = d_in[0];
    const void* ei = d_in[1];
    const float* emb = (const float*)d_in[2];
    const float* W1 = (const float*)d_in[3];
    const float* a_src1 = (const float*)d_in[4];
    const float* a_dst1 = (const float*)d_in[5];
    const float* b1 = (const float*)d_in[6];
    const float* W2 = (const float*)d_in[7];
    const float* a_src2 = (const float*)d_in[8];
    const float* a_dst2 = (const float*)d_in[9];
    const float* b2 = (const float*)d_in[10];
    float* out = (float*)d_out;

    int n = in_sizes[0];
    int e = in_sizes[1] / 2;

    int nb256 = (n + 255) / 256;
    int eb256 = (e + 255) / 256;
    int nwarp = (n + 7) / 8;
    int gb = (n + 63) / 64;
    int sb = (e + 1023) / 1024;   // scatter blocks: 256 thr x 4 edges
    int cb = (n + 7) / 8;         // emb-convert blocks: 8 warps/block, warp/node

    k_conv_idx<<<nb256 + cb, 256>>>(xidx, W1, W2, emb, n, nb256);
    k_conv_ei<<<eb256, 256>>>(ei, xidx, e);
    k_scan<<<nb256, 256>>>(n, e);

    k_gemm<1><<<gb + sb, 256>>>(a_src1, a_dst1, n, gb, sb, e);
    k_gather1<<<nwarp, 256>>>(b1, n);

    k_gemm<2><<<gb, 256>>>(a_src2, a_dst2, n, gb, 0, 0);
    k_gather2<<<nwarp, 256>>>(b2, out, n);
}